// round 9
// baseline (speedup 1.0000x reference)
#include <cuda_runtime.h>
#include <cuda_bf16.h>
#include <math.h>
#include <stdint.h>

#define NN 20000
#define EE 320000
#define IND 128
#define HH 8
#define CC 128
#define HCD 1024
#define GG 64
#define NEG_SLOPE 0.2f

// ---------------- scratch (static device globals; no allocation) ----------------
__device__ __nv_bfloat16 g_xl_bf[(size_t)NN * HCD];   // x@Wl+bl (41 MB)
__device__ __nv_bfloat16 g_xr_bf[(size_t)NN * HCD];   // x@Wr+br (41 MB)
__device__ float g_out[(size_t)NN * HCD];             // residual -> attn output (82 MB)
__device__ float g_h[(size_t)NN * CC];                // ELU(Linear) (10 MB)
__device__ int   g_deg[NN];                           // zero at load; re-zeroed by scan_k
__device__ int   g_rowptr[NN + 1];
__device__ int   g_cursor[NN];
__device__ int   g_adj[EE];
__device__ float g_pooled[GG * CC];

// ---------------- CSR build ----------------
__global__ void deg_k(const int* __restrict__ ei) {
    int e = blockIdx.x * 256 + threadIdx.x;
    if (e < EE) atomicAdd(&g_deg[ei[EE + e]], 1);
}

// scan + re-zero g_deg (so deg_k finds zeros on the next graph replay)
__global__ void scan_k() {
    __shared__ int warp_sums[32];
    int tid = threadIdx.x;
    int start = tid * 20;
    int v[20];
    int tot = 0;
#pragma unroll
    for (int j = 0; j < 20; j++) {
        int idx = start + j;
        int d = (idx < NN) ? g_deg[idx] : 0;
        v[j] = tot;
        tot += d;
    }
#pragma unroll
    for (int j = 0; j < 20; j++) {
        int idx = start + j;
        if (idx < NN) g_deg[idx] = 0;   // own elements only; no cross-thread hazard
    }
    int lane = tid & 31, wid = tid >> 5;
    int x = tot;
#pragma unroll
    for (int off = 1; off < 32; off <<= 1) {
        int t = __shfl_up_sync(0xffffffffu, x, off);
        if (lane >= off) x += t;
    }
    if (lane == 31) warp_sums[wid] = x;
    __syncthreads();
    if (wid == 0) {
        int w = warp_sums[lane];
#pragma unroll
        for (int off = 1; off < 32; off <<= 1) {
            int t = __shfl_up_sync(0xffffffffu, w, off);
            if (lane >= off) w += t;
        }
        warp_sums[lane] = w;
    }
    __syncthreads();
    int base = x - tot + (wid > 0 ? warp_sums[wid - 1] : 0);
#pragma unroll
    for (int j = 0; j < 20; j++) {
        int idx = start + j;
        if (idx <= NN) {
            int ex = base + v[j];
            g_rowptr[idx] = ex;
            if (idx < NN) g_cursor[idx] = ex;
        }
    }
}

__global__ void adj_k(const int* __restrict__ ei) {
    int e = blockIdx.x * 256 + threadIdx.x;
    if (e < EE) {
        int pos = atomicAdd(&g_cursor[ei[EE + e]], 1);
        g_adj[pos] = e;
    }
}

// ---------------- common mma helpers ----------------
__device__ __forceinline__ uint32_t f2tf32(float v) {
    uint32_t o;
    asm("cvt.rna.tf32.f32 %0, %1;" : "=r"(o) : "f"(v));
    return o;
}

__device__ __forceinline__ void mma_tf32(float c[4], uint32_t a0, uint32_t a1,
                                         uint32_t a2, uint32_t a3, uint32_t b0, uint32_t b1) {
    asm volatile(
        "mma.sync.aligned.m16n8k8.row.col.f32.tf32.tf32.f32 "
        "{%0,%1,%2,%3},{%4,%5,%6,%7},{%8,%9},{%0,%1,%2,%3};"
        : "+f"(c[0]), "+f"(c[1]), "+f"(c[2]), "+f"(c[3])
        : "r"(a0), "r"(a1), "r"(a2), "r"(a3), "r"(b0), "r"(b1));
}

__device__ __forceinline__ void mma_bf16(float c[4], uint32_t a0, uint32_t a1,
                                         uint32_t a2, uint32_t a3, uint32_t b0, uint32_t b1) {
    asm volatile(
        "mma.sync.aligned.m16n8k16.row.col.f32.bf16.bf16.f32 "
        "{%0,%1,%2,%3},{%4,%5,%6,%7},{%8,%9},{%0,%1,%2,%3};"
        : "+f"(c[0]), "+f"(c[1]), "+f"(c[2]), "+f"(c[3])
        : "r"(a0), "r"(a1), "r"(a2), "r"(a3), "r"(b0), "r"(b1));
}

__device__ __forceinline__ uint32_t pack_bf16x2(float lo, float hi) {
    __nv_bfloat162 p = __floats2bfloat162_rn(lo, hi);
    return *(const uint32_t*)&p;
}

// ---------------- bf16 pipelined GEMM (modes 0/1: xl/xr, bf16 out) ----------------
__global__ __launch_bounds__(256) void gemm_bf16_k(
    const float* __restrict__ X, const float* __restrict__ W,
    const float* __restrict__ bias, int M, int K, int N, int mode) {
    __shared__ uint32_t s_a[2][128][18];   // packed bf16x2: 16 k2 + pad2
    __shared__ uint32_t s_b[2][16][132];   // packed bf16x2 along K: 128 n + pad4

    int tid = threadIdx.x;
    int lane = tid & 31, warp = tid >> 5;
    int wm = warp & 3, wn = warp >> 2;
    int m0 = wm * 32, n0 = wn * 64;
    int mBase = blockIdx.y * 128, nBase = blockIdx.x * 128;

    float acc[2][8][4];
#pragma unroll
    for (int mt = 0; mt < 2; mt++)
#pragma unroll
        for (int nt = 0; nt < 8; nt++)
#pragma unroll
            for (int c = 0; c < 4; c++) acc[mt][nt][c] = 0.f;

    int aRowBase = tid >> 3, aK4 = tid & 7;    // A: rows +32i, one float4 @ col aK4
    int bK2 = tid >> 4, bN4b = (tid & 15) * 2; // B: k2-pair row, 2 float4 col groups

    float4 aReg[4], b0Reg[2], b1Reg[2];

    // prologue: chunk 0
#pragma unroll
    for (int i = 0; i < 4; i++) {
        int gr = mBase + aRowBase + i * 32;
        aReg[i] = (gr < M) ? *(const float4*)&X[(size_t)gr * K + aK4 * 4]
                           : make_float4(0.f, 0.f, 0.f, 0.f);
    }
#pragma unroll
    for (int i = 0; i < 2; i++) {
        int n4 = bN4b + i;
        b0Reg[i] = *(const float4*)&W[(size_t)(bK2 * 2) * N + nBase + n4 * 4];
        b1Reg[i] = *(const float4*)&W[(size_t)(bK2 * 2 + 1) * N + nBase + n4 * 4];
    }

    int s = 0;
    for (int kb = 0; kb < K; kb += 32) {
        // store prefetched chunk -> smem[s]
#pragma unroll
        for (int i = 0; i < 4; i++) {
            int m = aRowBase + i * 32;
            s_a[s][m][aK4 * 2 + 0] = pack_bf16x2(aReg[i].x, aReg[i].y);
            s_a[s][m][aK4 * 2 + 1] = pack_bf16x2(aReg[i].z, aReg[i].w);
        }
#pragma unroll
        for (int i = 0; i < 2; i++) {
            int n4 = bN4b + i;
            s_b[s][bK2][n4 * 4 + 0] = pack_bf16x2(b0Reg[i].x, b1Reg[i].x);
            s_b[s][bK2][n4 * 4 + 1] = pack_bf16x2(b0Reg[i].y, b1Reg[i].y);
            s_b[s][bK2][n4 * 4 + 2] = pack_bf16x2(b0Reg[i].z, b1Reg[i].z);
            s_b[s][bK2][n4 * 4 + 3] = pack_bf16x2(b0Reg[i].w, b1Reg[i].w);
        }
        __syncthreads();

        // prefetch next chunk
        int kn = kb + 32;
        if (kn < K) {
#pragma unroll
            for (int i = 0; i < 4; i++) {
                int gr = mBase + aRowBase + i * 32;
                aReg[i] = (gr < M) ? *(const float4*)&X[(size_t)gr * K + kn + aK4 * 4]
                                   : make_float4(0.f, 0.f, 0.f, 0.f);
            }
#pragma unroll
            for (int i = 0; i < 2; i++) {
                int n4 = bN4b + i;
                b0Reg[i] = *(const float4*)&W[(size_t)(kn + bK2 * 2) * N + nBase + n4 * 4];
                b1Reg[i] = *(const float4*)&W[(size_t)(kn + bK2 * 2 + 1) * N + nBase + n4 * 4];
            }
        }

        // compute on smem[s]
#pragma unroll
        for (int kk = 0; kk < 2; kk++) {
            uint32_t a[2][4];
#pragma unroll
            for (int mt = 0; mt < 2; mt++) {
                int r = m0 + mt * 16 + (lane >> 2);
                int c = kk * 8 + (lane & 3);
                a[mt][0] = s_a[s][r][c];
                a[mt][1] = s_a[s][r + 8][c];
                a[mt][2] = s_a[s][r][c + 4];
                a[mt][3] = s_a[s][r + 8][c + 4];
            }
#pragma unroll
            for (int nt = 0; nt < 8; nt++) {
                int n = n0 + nt * 8 + (lane >> 2);
                uint32_t b0 = s_b[s][kk * 8 + (lane & 3)][n];
                uint32_t b1 = s_b[s][kk * 8 + (lane & 3) + 4][n];
                mma_bf16(acc[0][nt], a[0][0], a[0][1], a[0][2], a[0][3], b0, b1);
                mma_bf16(acc[1][nt], a[1][0], a[1][1], a[1][2], a[1][3], b0, b1);
            }
        }
        s ^= 1;
    }

#pragma unroll
    for (int mt = 0; mt < 2; mt++) {
#pragma unroll
        for (int nt = 0; nt < 8; nt++) {
            int r0 = mBase + m0 + mt * 16 + (lane >> 2);
            int cb = nBase + n0 + nt * 8 + (lane & 3) * 2;
            float bb0 = bias[cb], bb1 = bias[cb + 1];
            float v0 = acc[mt][nt][0] + bb0;
            float v1 = acc[mt][nt][1] + bb1;
            float v2 = acc[mt][nt][2] + bb0;
            float v3 = acc[mt][nt][3] + bb1;
            __nv_bfloat16* D = (mode == 0) ? g_xl_bf : g_xr_bf;
            if (r0 < M)
                *(__nv_bfloat162*)&D[(size_t)r0 * N + cb] = __floats2bfloat162_rn(v0, v1);
            if (r0 + 8 < M)
                *(__nv_bfloat162*)&D[(size_t)(r0 + 8) * N + cb] = __floats2bfloat162_rn(v2, v3);
        }
    }
}

// ---------------- tf32 pipelined GEMM (mode 2: residual f32; mode 3: ELU f32) ----------------
#define SA_STRIDE 36
#define SB_STRIDE 136
#define SA_STAGE (128 * SA_STRIDE)
#define SB_STAGE (32 * SB_STRIDE)
#define GEMM_SMEM_BYTES ((2 * SA_STAGE + 2 * SB_STAGE) * 4)

__global__ __launch_bounds__(256) void gemm_tf32_k(
    const float* __restrict__ Xf, int x_is_gout,
    const float* __restrict__ W, const float* __restrict__ bias,
    int M, int K, int N, int mode) {
    extern __shared__ uint32_t smem[];
    uint32_t* s_a = smem;
    uint32_t* s_b = smem + 2 * SA_STAGE;

    const float* X = x_is_gout ? g_out : Xf;
    int tid = threadIdx.x;
    int lane = tid & 31, warp = tid >> 5;
    int wm = warp & 3, wn = warp >> 2;
    int m0 = wm * 32, n0 = wn * 64;
    int mBase = blockIdx.y * 128, nBase = blockIdx.x * 128;

    float acc[2][8][4];
#pragma unroll
    for (int mt = 0; mt < 2; mt++)
#pragma unroll
        for (int nt = 0; nt < 8; nt++)
#pragma unroll
            for (int c = 0; c < 4; c++) acc[mt][nt][c] = 0.f;

    int aRowBase = tid >> 3, aK4 = tid & 7;
    int bK = tid >> 3, bC = tid & 7;

    float4 aReg[4], bReg[4];
#pragma unroll
    for (int i = 0; i < 4; i++) {
        int gr = mBase + aRowBase + i * 32;
        aReg[i] = (gr < M) ? *(const float4*)&X[(size_t)gr * K + aK4 * 4]
                           : make_float4(0.f, 0.f, 0.f, 0.f);
        bReg[i] = *(const float4*)&W[(size_t)bK * N + nBase + (bC + 8 * i) * 4];
    }

    int s = 0;
    for (int kb = 0; kb < K; kb += 32) {
#pragma unroll
        for (int i = 0; i < 4; i++) {
            int m = aRowBase + i * 32;
            uint4 at = make_uint4(f2tf32(aReg[i].x), f2tf32(aReg[i].y),
                                  f2tf32(aReg[i].z), f2tf32(aReg[i].w));
            *(uint4*)&s_a[s * SA_STAGE + m * SA_STRIDE + aK4 * 4] = at;
            uint4 bt = make_uint4(f2tf32(bReg[i].x), f2tf32(bReg[i].y),
                                  f2tf32(bReg[i].z), f2tf32(bReg[i].w));
            *(uint4*)&s_b[s * SB_STAGE + bK * SB_STRIDE + (bC + 8 * i) * 4] = bt;
        }
        __syncthreads();

        int kn = kb + 32;
        if (kn < K) {
#pragma unroll
            for (int i = 0; i < 4; i++) {
                int gr = mBase + aRowBase + i * 32;
                aReg[i] = (gr < M) ? *(const float4*)&X[(size_t)gr * K + kn + aK4 * 4]
                                   : make_float4(0.f, 0.f, 0.f, 0.f);
                bReg[i] = *(const float4*)&W[(size_t)(kn + bK) * N + nBase + (bC + 8 * i) * 4];
            }
        }

        const uint32_t* pa = &s_a[s * SA_STAGE];
        const uint32_t* pb = &s_b[s * SB_STAGE];
#pragma unroll
        for (int kk = 0; kk < 4; kk++) {
            uint32_t a[2][4];
#pragma unroll
            for (int mt = 0; mt < 2; mt++) {
                int r = m0 + mt * 16 + (lane >> 2);
                int c = kk * 8 + (lane & 3);
                a[mt][0] = pa[r * SA_STRIDE + c];
                a[mt][1] = pa[(r + 8) * SA_STRIDE + c];
                a[mt][2] = pa[r * SA_STRIDE + c + 4];
                a[mt][3] = pa[(r + 8) * SA_STRIDE + c + 4];
            }
#pragma unroll
            for (int nt = 0; nt < 8; nt++) {
                int n = n0 + nt * 8 + (lane >> 2);
                uint32_t b0 = pb[(kk * 8 + (lane & 3)) * SB_STRIDE + n];
                uint32_t b1 = pb[(kk * 8 + (lane & 3) + 4) * SB_STRIDE + n];
                mma_tf32(acc[0][nt], a[0][0], a[0][1], a[0][2], a[0][3], b0, b1);
                mma_tf32(acc[1][nt], a[1][0], a[1][1], a[1][2], a[1][3], b0, b1);
            }
        }
        s ^= 1;
    }

#pragma unroll
    for (int mt = 0; mt < 2; mt++) {
#pragma unroll
        for (int nt = 0; nt < 8; nt++) {
            int r0 = mBase + m0 + mt * 16 + (lane >> 2);
            int cb = nBase + n0 + nt * 8 + (lane & 3) * 2;
            float bb0 = bias[cb], bb1 = bias[cb + 1];
            float v0 = acc[mt][nt][0] + bb0;
            float v1 = acc[mt][nt][1] + bb1;
            float v2 = acc[mt][nt][2] + bb0;
            float v3 = acc[mt][nt][3] + bb1;
            if (mode == 3) {
                v0 = v0 > 0.f ? v0 : (__expf(v0) - 1.f);
                v1 = v1 > 0.f ? v1 : (__expf(v1) - 1.f);
                v2 = v2 > 0.f ? v2 : (__expf(v2) - 1.f);
                v3 = v3 > 0.f ? v3 : (__expf(v3) - 1.f);
                if (r0 < M) *(float2*)&g_h[(size_t)r0 * N + cb] = make_float2(v0, v1);
                if (r0 + 8 < M) *(float2*)&g_h[(size_t)(r0 + 8) * N + cb] = make_float2(v2, v3);
            } else {
                if (r0 < M) *(float2*)&g_out[(size_t)r0 * N + cb] = make_float2(v0, v1);
                if (r0 + 8 < M) *(float2*)&g_out[(size_t)(r0 + 8) * N + cb] = make_float2(v2, v3);
            }
        }
    }
}

// ---------------- fused per-node GATv2 with smem-staged xl rows ----------------
#define CHKF 16
__global__ __launch_bounds__(256) void node_attn_k(const int* __restrict__ ei,
                                                   const float* __restrict__ att) {
    int i = blockIdx.x;
    int tid = threadIdx.x, lane = tid & 31, wid = tid >> 5;
    int beg = g_rowptr[i], end = g_rowptr[i + 1];

    __shared__ float s_att[HCD];
    __shared__ float s_xr[HCD];
    __shared__ __nv_bfloat16 s_xl[CHKF][HCD];
    __shared__ float s_logit[CHKF][9];
    __shared__ float s_scale[HH];
    __shared__ float s_inv[HH];

#pragma unroll
    for (int q = 0; q < 4; q++) s_att[tid + q * 256] = att[tid + q * 256];
    if (tid < 128) {
        uint4 raw = ((const uint4*)&g_xr_bf[(size_t)i * HCD])[tid];
        const __nv_bfloat162* p = (const __nv_bfloat162*)&raw;
#pragma unroll
        for (int q = 0; q < 4; q++) {
            float2 f = __bfloat1622float2(p[q]);
            s_xr[tid * 8 + q * 2 + 0] = f.x;
            s_xr[tid * 8 + q * 2 + 1] = f.y;
        }
    }
    __syncthreads();

    float run_m = -3.4e38f, run_s = 0.f;
    float acc0 = 0.f, acc1 = 0.f, acc2 = 0.f, acc3 = 0.f;
    int h = tid >> 5;

    for (int cb = beg; cb < end; cb += CHKF) {
        int cnt = min(CHKF, end - cb);

        // phase 1: logits + stage xl rows into smem (warp per edge)
        for (int k = wid; k < cnt; k += 8) {
            int eid = g_adj[cb + k];
            int src = ei[eid];
            const uint4* A = (const uint4*)&g_xl_bf[(size_t)src * HCD];
            uint4* S = (uint4*)&s_xl[k][0];
#pragma unroll
            for (int it = 0; it < 4; it++) {
                int j = it * 32 + lane;
                uint4 av = A[j];
                S[j] = av;
                const __nv_bfloat162* ap = (const __nv_bfloat162*)&av;
                float v = 0.f;
#pragma unroll
                for (int q = 0; q < 4; q++) {
                    float2 fa = __bfloat1622float2(ap[q]);
                    float sx = fa.x + s_xr[j * 8 + q * 2];
                    float sy = fa.y + s_xr[j * 8 + q * 2 + 1];
                    sx = sx > 0.f ? sx : NEG_SLOPE * sx;
                    sy = sy > 0.f ? sy : NEG_SLOPE * sy;
                    v += sx * s_att[j * 8 + q * 2] + sy * s_att[j * 8 + q * 2 + 1];
                }
#pragma unroll
                for (int off = 8; off > 0; off >>= 1)
                    v += __shfl_down_sync(0xffffffffu, v, off, 16);
                if ((lane & 15) == 0) s_logit[k][it * 2 + (lane >> 4)] = v;
            }
        }
        __syncthreads();

        // phase 2: per-head streaming stats (warp wid = head wid)
        {
            float cm = -3.4e38f;
            for (int k = lane; k < cnt; k += 32) cm = fmaxf(cm, s_logit[k][wid]);
#pragma unroll
            for (int off = 16; off > 0; off >>= 1)
                cm = fmaxf(cm, __shfl_xor_sync(0xffffffffu, cm, off));
            float nm = fmaxf(run_m, cm);
            float csum = 0.f;
            for (int k = lane; k < cnt; k += 32) {
                float w = __expf(s_logit[k][wid] - nm);
                s_logit[k][wid] = w;
                csum += w;
            }
#pragma unroll
            for (int off = 16; off > 0; off >>= 1)
                csum += __shfl_xor_sync(0xffffffffu, csum, off);
            float scale = __expf(run_m - nm);
            run_s = run_s * scale + csum;
            run_m = nm;
            if (lane == 0) s_scale[wid] = scale;
        }
        __syncthreads();

        // phase 3: weighted aggregate from smem
        float sc = s_scale[h];
        acc0 *= sc; acc1 *= sc; acc2 *= sc; acc3 *= sc;
        for (int k = 0; k < cnt; k++) {
            float a = s_logit[k][h];
            uint2 raw = ((const uint2*)&s_xl[k][0])[tid];
            float2 p0 = __bfloat1622float2(*(const __nv_bfloat162*)&raw.x);
            float2 p1 = __bfloat1622float2(*(const __nv_bfloat162*)&raw.y);
            acc0 += a * p0.x;
            acc1 += a * p0.y;
            acc2 += a * p1.x;
            acc3 += a * p1.y;
        }
        __syncthreads();
    }

    if (lane == 0) s_inv[wid] = (run_s > 0.f) ? 1.f / run_s : 0.f;
    __syncthreads();
    float inv = s_inv[h];

    float4* orow = (float4*)&g_out[(size_t)i * HCD];
    float4 r = orow[tid];
    orow[tid] = make_float4(acc0 * inv + r.x, acc1 * inv + r.y,
                            acc2 * inv + r.z, acc3 * inv + r.w);
}

// ---------------- deterministic mean pool (batch sorted) ----------------
__global__ void pool_k(const int* __restrict__ batch) {
    int g = blockIdx.x;
    __shared__ int sb, se;
    __shared__ float red[256];
    if (threadIdx.x == 0) {
        int lo = 0, hi = NN;
        while (lo < hi) { int mid = (lo + hi) >> 1; if (batch[mid] < g) lo = mid + 1; else hi = mid; }
        sb = lo;
        lo = 0; hi = NN;
        while (lo < hi) { int mid = (lo + hi) >> 1; if (batch[mid] <= g) lo = mid + 1; else hi = mid; }
        se = lo;
    }
    __syncthreads();
    int beg = sb, end = se;
    int ch = threadIdx.x & 127, half = threadIdx.x >> 7;
    float acc = 0.f;
    for (int n = beg + half; n < end; n += 2) acc += g_h[(size_t)n * CC + ch];
    red[threadIdx.x] = acc;
    __syncthreads();
    if (half == 0) {
        float v = red[ch] + red[128 + ch];
        float c = (end > beg) ? (float)(end - beg) : 1.f;
        g_pooled[g * CC + ch] = v / c;
    }
}

// ---------------- MLP head ----------------
__global__ void head_k(const float* __restrict__ W1, const float* __restrict__ b1,
                       const float* __restrict__ W2, const float* __restrict__ b2,
                       const float* __restrict__ W3, const float* __restrict__ b3,
                       float* __restrict__ out) {
    __shared__ float sp[GG][CC];
    __shared__ float h1[GG][16];
    __shared__ float h2[GG][32];
    int tid = threadIdx.x;
    for (int idx = tid; idx < GG * CC; idx += 256) sp[idx >> 7][idx & 127] = g_pooled[idx];
    __syncthreads();
    for (int idx = tid; idx < GG * 16; idx += 256) {
        int g = idx / 16, o = idx % 16;
        float s = b1[o];
        for (int k = 0; k < CC; k++) s += sp[g][k] * W1[k * 16 + o];
        h1[g][o] = s > 0.f ? s : 0.f;
    }
    __syncthreads();
    for (int idx = tid; idx < GG * 32; idx += 256) {
        int g = idx / 32, o = idx % 32;
        float s = b2[o];
        for (int k = 0; k < 16; k++) s += h1[g][k] * W2[k * 32 + o];
        h2[g][o] = s > 0.f ? s : 0.f;
    }
    __syncthreads();
    for (int idx = tid; idx < GG * 5; idx += 256) {
        int g = idx / 5, o = idx % 5;
        float s = b3[o];
        for (int k = 0; k < 32; k++) s += h2[g][k] * W3[k * 5 + o];
        out[idx] = s;
    }
}

// ---------------- launch ----------------
extern "C" void kernel_launch(void* const* d_in, const int* in_sizes, int n_in,
                              void* d_out, int out_size) {
    const float* x = (const float*)d_in[0];
    const int* ei = (const int*)d_in[1];
    const int* batch = (const int*)d_in[2];
    const float* Wl = (const float*)d_in[3];
    const float* bl = (const float*)d_in[4];
    const float* Wr = (const float*)d_in[5];
    const float* br = (const float*)d_in[6];
    const float* att = (const float*)d_in[7];
    const float* Wres = (const float*)d_in[8];
    const float* bias_attn = (const float*)d_in[9];
    const float* W_lin = (const float*)d_in[10];
    const float* b_lin = (const float*)d_in[11];
    const float* W1 = (const float*)d_in[12];
    const float* b1 = (const float*)d_in[13];
    const float* W2 = (const float*)d_in[14];
    const float* b2 = (const float*)d_in[15];
    const float* W3 = (const float*)d_in[16];
    const float* b3 = (const float*)d_in[17];
    float* out = (float*)d_out;

    cudaFuncSetAttribute(gemm_tf32_k, cudaFuncAttributeMaxDynamicSharedMemorySize,
                         GEMM_SMEM_BYTES);

    // CSR build (scan_k re-zeroes g_deg for the next replay)
    deg_k<<<(EE + 255) / 256, 256>>>(ei);
    scan_k<<<1, 1024>>>();
    adj_k<<<(EE + 255) / 256, 256>>>(ei);

    // dense transforms
    dim3 blk(256);
    dim3 g1(HCD / 128, (NN + 127) / 128);
    gemm_bf16_k<<<g1, blk>>>(x, Wl, bl, NN, IND, HCD, 0);                         // 4th launch (profiled)
    gemm_bf16_k<<<g1, blk>>>(x, Wr, br, NN, IND, HCD, 1);
    gemm_tf32_k<<<g1, blk, GEMM_SMEM_BYTES>>>(x, 0, Wres, bias_attn, NN, IND, HCD, 2);

    // fused GATv2 attention
    node_attn_k<<<NN, 256>>>(ei, att);

    // Linear + ELU
    dim3 g2(CC / 128, (NN + 127) / 128);
    gemm_tf32_k<<<g2, blk, GEMM_SMEM_BYTES>>>(nullptr, 1, W_lin, b_lin, NN, HCD, CC, 3);

    // pool + head
    pool_k<<<GG, 256>>>(batch);
    head_k<<<1, 256>>>(W1, b1, W2, b2, W3, b3, out);
}

// round 10
// speedup vs baseline: 1.0119x; 1.0119x over previous
#include <cuda_runtime.h>
#include <cuda_bf16.h>
#include <math.h>
#include <stdint.h>

#define NN 20000
#define EE 320000
#define IND 128
#define HH 8
#define CC 128
#define HCD 1024
#define GG 64
#define NEG_SLOPE 0.2f

// ---------------- scratch (static device globals; no allocation) ----------------
__device__ __nv_bfloat16 g_x_bf[(size_t)NN * IND];    // x pre-converted (5 MB)
__device__ uint32_t g_wl_pk[64 * HCD];                // Wl K-pair-packed bf16x2
__device__ uint32_t g_wr_pk[64 * HCD];                // Wr K-pair-packed bf16x2
__device__ __nv_bfloat16 g_xl_bf[(size_t)NN * HCD];   // x@Wl+bl (41 MB)
__device__ __nv_bfloat16 g_xr_bf[(size_t)NN * HCD];   // x@Wr+br (41 MB)
__device__ float g_out[(size_t)NN * HCD];             // attn aggregate, then +residual (82 MB)
__device__ float g_h[(size_t)NN * CC];                // ELU(Linear) (10 MB)
__device__ int   g_deg[NN];                           // zero at load; re-zeroed by scan_k
__device__ int   g_rowptr[NN + 1];
__device__ int   g_cursor[NN];
__device__ int   g_adj[EE];
__device__ float g_pooled[GG * CC];

__device__ __forceinline__ uint32_t pack_bf16x2(float lo, float hi) {
    __nv_bfloat162 p = __floats2bfloat162_rn(lo, hi);
    return *(const uint32_t*)&p;
}

// ---------------- prep (deg atomics + x->bf16 + W->packed bf16), one launch ----------------
#define DEG_BLOCKS 1250
#define XCV_BLOCKS 2500
#define WPK_BLOCKS 512

__global__ void prep_deg_k(const int* __restrict__ ei, const float* __restrict__ x,
                           const float* __restrict__ Wl, const float* __restrict__ Wr) {
    int b = blockIdx.x, tid = threadIdx.x;
    if (b < DEG_BLOCKS) {
        int e = b * 256 + tid;
        if (e < EE) atomicAdd(&g_deg[ei[EE + e]], 1);
    } else if (b < DEG_BLOCKS + XCV_BLOCKS) {
        int t = (b - DEG_BLOCKS) * 256 + tid;   // < 640000 (float4 units)
        float4 v = ((const float4*)x)[t];
        uint2 o;
        o.x = pack_bf16x2(v.x, v.y);
        o.y = pack_bf16x2(v.z, v.w);
        ((uint2*)g_x_bf)[t] = o;
    } else {
        int t = (b - DEG_BLOCKS - XCV_BLOCKS) * 256 + tid;  // < 131072
        int w = t >> 16;
        int r = t & 65535;          // k2*1024 + n
        int k2 = r >> 10, n = r & 1023;
        const float* W = w ? Wr : Wl;
        uint32_t pk = pack_bf16x2(W[(2 * k2) * HCD + n], W[(2 * k2 + 1) * HCD + n]);
        (w ? g_wr_pk : g_wl_pk)[r] = pk;
    }
}

// ---------------- scan (re-zeroes g_deg for replay) ----------------
__global__ void scan_k() {
    __shared__ int warp_sums[32];
    int tid = threadIdx.x;
    int start = tid * 20;
    int v[20];
    int tot = 0;
#pragma unroll
    for (int j = 0; j < 20; j++) {
        int idx = start + j;
        int d = (idx < NN) ? g_deg[idx] : 0;
        v[j] = tot;
        tot += d;
    }
#pragma unroll
    for (int j = 0; j < 20; j++) {
        int idx = start + j;
        if (idx < NN) g_deg[idx] = 0;
    }
    int lane = tid & 31, wid = tid >> 5;
    int x = tot;
#pragma unroll
    for (int off = 1; off < 32; off <<= 1) {
        int t = __shfl_up_sync(0xffffffffu, x, off);
        if (lane >= off) x += t;
    }
    if (lane == 31) warp_sums[wid] = x;
    __syncthreads();
    if (wid == 0) {
        int w = warp_sums[lane];
#pragma unroll
        for (int off = 1; off < 32; off <<= 1) {
            int t = __shfl_up_sync(0xffffffffu, w, off);
            if (lane >= off) w += t;
        }
        warp_sums[lane] = w;
    }
    __syncthreads();
    int base = x - tot + (wid > 0 ? warp_sums[wid - 1] : 0);
#pragma unroll
    for (int j = 0; j < 20; j++) {
        int idx = start + j;
        if (idx <= NN) {
            int ex = base + v[j];
            g_rowptr[idx] = ex;
            if (idx < NN) g_cursor[idx] = ex;
        }
    }
}

// ---------------- mma helpers ----------------
__device__ __forceinline__ uint32_t f2tf32(float v) {
    uint32_t o;
    asm("cvt.rna.tf32.f32 %0, %1;" : "=r"(o) : "f"(v));
    return o;
}

__device__ __forceinline__ void mma_tf32(float c[4], uint32_t a0, uint32_t a1,
                                         uint32_t a2, uint32_t a3, uint32_t b0, uint32_t b1) {
    asm volatile(
        "mma.sync.aligned.m16n8k8.row.col.f32.tf32.tf32.f32 "
        "{%0,%1,%2,%3},{%4,%5,%6,%7},{%8,%9},{%0,%1,%2,%3};"
        : "+f"(c[0]), "+f"(c[1]), "+f"(c[2]), "+f"(c[3])
        : "r"(a0), "r"(a1), "r"(a2), "r"(a3), "r"(b0), "r"(b1));
}

__device__ __forceinline__ void mma_bf16(float c[4], uint32_t a0, uint32_t a1,
                                         uint32_t a2, uint32_t a3, uint32_t b0, uint32_t b1) {
    asm volatile(
        "mma.sync.aligned.m16n8k16.row.col.f32.bf16.bf16.f32 "
        "{%0,%1,%2,%3},{%4,%5,%6,%7},{%8,%9},{%0,%1,%2,%3};"
        : "+f"(c[0]), "+f"(c[1]), "+f"(c[2]), "+f"(c[3])
        : "r"(a0), "r"(a1), "r"(a2), "r"(a3), "r"(b0), "r"(b1));
}

__device__ __forceinline__ void cp16(uint32_t dst, const void* src, int sz) {
    asm volatile("cp.async.cg.shared.global [%0], [%1], 16, %2;"
                 :: "r"(dst), "l"(src), "r"(sz));
}
__device__ __forceinline__ void cp_commit() { asm volatile("cp.async.commit_group;"); }

// ---------------- fused adj + xl/xr bf16 cp.async GEMM ----------------
#define ADJ_BLOCKS 1250
#define GEMM_BLOCKS_PER 1256   // 157 m-tiles * 8 n-tiles
#define ASTR 20                // A row stride in u32 (16 data + 4 pad), 80B rows (16B aligned)
#define BSTR 136               // B row stride in u32 (128 data + 8 pad), 544B rows
#define A_ST (128 * ASTR)      // 2560 u32
#define B_ST (16 * BSTR)       // 2176 u32
#define STAGE_U32 (A_ST + B_ST)
#define NSTAGE 3
#define AG_SMEM (NSTAGE * STAGE_U32 * 4)   // 56832 B

__global__ __launch_bounds__(256) void adjgemm_k(const int* __restrict__ ei,
                                                 const float* __restrict__ bl,
                                                 const float* __restrict__ br) {
    int b = blockIdx.x, tid = threadIdx.x;
    if (b < ADJ_BLOCKS) {
        int e = b * 256 + tid;
        if (e < EE) {
            int pos = atomicAdd(&g_cursor[ei[EE + e]], 1);
            g_adj[pos] = e;
        }
        return;
    }
    extern __shared__ uint32_t sm[];
    int gb = b - ADJ_BLOCKS;
    int z = gb / GEMM_BLOCKS_PER;
    int t = gb % GEMM_BLOCKS_PER;
    int nBase = (t & 7) * 128;
    int mBase = (t >> 3) * 128;
    const uint32_t* Wpk = z ? g_wr_pk : g_wl_pk;
    const float* bias = z ? br : bl;
    __nv_bfloat16* D = z ? g_xr_bf : g_xl_bf;

    int lane = tid & 31, warp = tid >> 5;
    int wm = warp & 3, wn = warp >> 2;
    int m0 = wm * 32, n0 = wn * 64;

    uint32_t smBase = (uint32_t)__cvta_generic_to_shared(sm);

    auto issue = [&](int c) {
        int s = c % NSTAGE;
        uint32_t aAddr = smBase + (s * STAGE_U32) * 4;
        uint32_t bAddr = aAddr + A_ST * 4;
#pragma unroll
        for (int i = 0; i < 2; i++) {
            int q = tid + i * 256;
            int m = q >> 2, c4 = q & 3;
            int gr = mBase + m;
            const void* src = &g_x_bf[(size_t)min(gr, NN - 1) * IND + c * 32 + c4 * 8];
            cp16(aAddr + (m * ASTR + c4 * 4) * 4, src, gr < NN ? 16 : 0);
        }
#pragma unroll
        for (int i = 0; i < 2; i++) {
            int q = tid + i * 256;
            int k2 = q >> 5, sub = q & 31;
            const void* src = &Wpk[(c * 16 + k2) * HCD + nBase + sub * 4];
            cp16(bAddr + (k2 * BSTR + sub * 4) * 4, src, 16);
        }
        cp_commit();
    };

    float acc[2][8][4];
#pragma unroll
    for (int mt = 0; mt < 2; mt++)
#pragma unroll
        for (int nt = 0; nt < 8; nt++)
#pragma unroll
            for (int c = 0; c < 4; c++) acc[mt][nt][c] = 0.f;

    issue(0);
    issue(1);

#pragma unroll
    for (int c = 0; c < 4; c++) {
        if (c < 3) asm volatile("cp.async.wait_group 1;" ::: "memory");
        else       asm volatile("cp.async.wait_group 0;" ::: "memory");
        __syncthreads();
        if (c + 2 < 4) issue(c + 2);

        const uint32_t* sa = sm + (c % NSTAGE) * STAGE_U32;
        const uint32_t* sb = sa + A_ST;
#pragma unroll
        for (int kk = 0; kk < 2; kk++) {
            uint32_t a[2][4];
            int cidx = kk * 8 + (lane & 3);
#pragma unroll
            for (int mt = 0; mt < 2; mt++) {
                int r = m0 + mt * 16 + (lane >> 2);
                a[mt][0] = sa[r * ASTR + cidx];
                a[mt][1] = sa[(r + 8) * ASTR + cidx];
                a[mt][2] = sa[r * ASTR + cidx + 4];
                a[mt][3] = sa[(r + 8) * ASTR + cidx + 4];
            }
#pragma unroll
            for (int nt = 0; nt < 8; nt++) {
                int n = n0 + nt * 8 + (lane >> 2);
                uint32_t b0 = sb[(kk * 8 + (lane & 3)) * BSTR + n];
                uint32_t b1 = sb[(kk * 8 + (lane & 3) + 4) * BSTR + n];
                mma_bf16(acc[0][nt], a[0][0], a[0][1], a[0][2], a[0][3], b0, b1);
                mma_bf16(acc[1][nt], a[1][0], a[1][1], a[1][2], a[1][3], b0, b1);
            }
        }
        __syncthreads();
    }

#pragma unroll
    for (int mt = 0; mt < 2; mt++) {
#pragma unroll
        for (int nt = 0; nt < 8; nt++) {
            int r0 = mBase + m0 + mt * 16 + (lane >> 2);
            int cb = nBase + n0 + nt * 8 + (lane & 3) * 2;
            float bb0 = bias[cb], bb1 = bias[cb + 1];
            float v0 = acc[mt][nt][0] + bb0;
            float v1 = acc[mt][nt][1] + bb1;
            float v2 = acc[mt][nt][2] + bb0;
            float v3 = acc[mt][nt][3] + bb1;
            if (r0 < NN)
                *(__nv_bfloat162*)&D[(size_t)r0 * HCD + cb] = __floats2bfloat162_rn(v0, v1);
            if (r0 + 8 < NN)
                *(__nv_bfloat162*)&D[(size_t)(r0 + 8) * HCD + cb] = __floats2bfloat162_rn(v2, v3);
        }
    }
}

// ---------------- tf32 pipelined GEMM, templated warp-N (mode 2: RMW g_out; 3: ELU g_h) ----------------
#define SA_STRIDE 36
#define SA_STAGE (128 * SA_STRIDE)

template <int NTW>
__global__ __launch_bounds__(256) void gemm_tf32_k(
    const float* __restrict__ Xf, int x_is_gout,
    const float* __restrict__ W, const float* __restrict__ bias,
    int M, int K, int N, int mode) {
    constexpr int BN = NTW * 16;        // block N tile
    constexpr int SBS = BN + 8;         // B row stride (u32)
    constexpr int SB_STAGE = 32 * SBS;
    constexpr int BI = BN / 32;         // float4 col-groups per thread

    extern __shared__ uint32_t smem[];
    uint32_t* s_a = smem;
    uint32_t* s_b = smem + 2 * SA_STAGE;

    const float* X = x_is_gout ? g_out : Xf;
    int tid = threadIdx.x;
    int lane = tid & 31, warp = tid >> 5;
    int wm = warp & 3, wn = warp >> 2;
    int m0 = wm * 32, n0 = wn * (NTW * 8);
    int mBase = blockIdx.y * 128, nBase = blockIdx.x * BN;

    float acc[2][NTW][4];
#pragma unroll
    for (int mt = 0; mt < 2; mt++)
#pragma unroll
        for (int nt = 0; nt < NTW; nt++)
#pragma unroll
            for (int c = 0; c < 4; c++) acc[mt][nt][c] = 0.f;

    int aRowBase = tid >> 3, aK4 = tid & 7;
    int bK = tid >> 3, bC = tid & 7;

    float4 aReg[4], bReg[BI];
#pragma unroll
    for (int i = 0; i < 4; i++) {
        int gr = mBase + aRowBase + i * 32;
        aReg[i] = (gr < M) ? *(const float4*)&X[(size_t)gr * K + aK4 * 4]
                           : make_float4(0.f, 0.f, 0.f, 0.f);
    }
#pragma unroll
    for (int i = 0; i < BI; i++)
        bReg[i] = *(const float4*)&W[(size_t)bK * N + nBase + (bC + 8 * i) * 4];

    int s = 0;
    for (int kb = 0; kb < K; kb += 32) {
#pragma unroll
        for (int i = 0; i < 4; i++) {
            int m = aRowBase + i * 32;
            uint4 at = make_uint4(f2tf32(aReg[i].x), f2tf32(aReg[i].y),
                                  f2tf32(aReg[i].z), f2tf32(aReg[i].w));
            *(uint4*)&s_a[s * SA_STAGE + m * SA_STRIDE + aK4 * 4] = at;
        }
#pragma unroll
        for (int i = 0; i < BI; i++) {
            uint4 bt = make_uint4(f2tf32(bReg[i].x), f2tf32(bReg[i].y),
                                  f2tf32(bReg[i].z), f2tf32(bReg[i].w));
            *(uint4*)&s_b[s * SB_STAGE + bK * SBS + (bC + 8 * i) * 4] = bt;
        }
        __syncthreads();

        int kn = kb + 32;
        if (kn < K) {
#pragma unroll
            for (int i = 0; i < 4; i++) {
                int gr = mBase + aRowBase + i * 32;
                aReg[i] = (gr < M) ? *(const float4*)&X[(size_t)gr * K + kn + aK4 * 4]
                                   : make_float4(0.f, 0.f, 0.f, 0.f);
            }
#pragma unroll
            for (int i = 0; i < BI; i++)
                bReg[i] = *(const float4*)&W[(size_t)(kn + bK) * N + nBase + (bC + 8 * i) * 4];
        }

        const uint32_t* pa = &s_a[s * SA_STAGE];
        const uint32_t* pb = &s_b[s * SB_STAGE];
#pragma unroll
        for (int kk = 0; kk < 4; kk++) {
            uint32_t a[2][4];
#pragma unroll
            for (int mt = 0; mt < 2; mt++) {
                int r = m0 + mt * 16 + (lane >> 2);
                int c = kk * 8 + (lane & 3);
                a[mt][0] = pa[r * SA_STRIDE + c];
                a[mt][1] = pa[(r + 8) * SA_STRIDE + c];
                a[mt][2] = pa[r * SA_STRIDE + c + 4];
                a[mt][3] = pa[(r + 8) * SA_STRIDE + c + 4];
            }
#pragma unroll
            for (int nt = 0; nt < NTW; nt++) {
                int n = n0 + nt * 8 + (lane >> 2);
                uint32_t b0 = pb[(kk * 8 + (lane & 3)) * SBS + n];
                uint32_t b1 = pb[(kk * 8 + (lane & 3) + 4) * SBS + n];
                mma_tf32(acc[0][nt], a[0][0], a[0][1], a[0][2], a[0][3], b0, b1);
                mma_tf32(acc[1][nt], a[1][0], a[1][1], a[1][2], a[1][3], b0, b1);
            }
        }
        __syncthreads();
        s ^= 1;
    }

#pragma unroll
    for (int mt = 0; mt < 2; mt++) {
#pragma unroll
        for (int nt = 0; nt < NTW; nt++) {
            int r0 = mBase + m0 + mt * 16 + (lane >> 2);
            int cb = nBase + n0 + nt * 8 + (lane & 3) * 2;
            float bb0 = bias[cb], bb1 = bias[cb + 1];
            float v0 = acc[mt][nt][0] + bb0;
            float v1 = acc[mt][nt][1] + bb1;
            float v2 = acc[mt][nt][2] + bb0;
            float v3 = acc[mt][nt][3] + bb1;
            if (mode == 3) {
                v0 = v0 > 0.f ? v0 : (__expf(v0) - 1.f);
                v1 = v1 > 0.f ? v1 : (__expf(v1) - 1.f);
                v2 = v2 > 0.f ? v2 : (__expf(v2) - 1.f);
                v3 = v3 > 0.f ? v3 : (__expf(v3) - 1.f);
                if (r0 < M) *(float2*)&g_h[(size_t)r0 * N + cb] = make_float2(v0, v1);
                if (r0 + 8 < M) *(float2*)&g_h[(size_t)(r0 + 8) * N + cb] = make_float2(v2, v3);
            } else {
                // mode 2: RMW-add residual onto attn aggregate already in g_out
                if (r0 < M) {
                    float2 p = *(float2*)&g_out[(size_t)r0 * N + cb];
                    *(float2*)&g_out[(size_t)r0 * N + cb] = make_float2(v0 + p.x, v1 + p.y);
                }
                if (r0 + 8 < M) {
                    float2 p = *(float2*)&g_out[(size_t)(r0 + 8) * N + cb];
                    *(float2*)&g_out[(size_t)(r0 + 8) * N + cb] = make_float2(v2 + p.x, v3 + p.y);
                }
            }
        }
    }
}

// ---------------- fused per-node GATv2 (stores pure aggregate; residual added by mode2) ----------------
#define CHKF 16
__global__ __launch_bounds__(256) void node_attn_k(const int* __restrict__ ei,
                                                   const float* __restrict__ att) {
    int i = blockIdx.x;
    int tid = threadIdx.x, lane = tid & 31, wid = tid >> 5;
    int beg = g_rowptr[i], end = g_rowptr[i + 1];

    __shared__ float s_att[HCD];
    __shared__ float s_xr[HCD];
    __shared__ __nv_bfloat16 s_xl[CHKF][HCD];
    __shared__ float s_logit[CHKF][9];
    __shared__ float s_scale[HH];
    __shared__ float s_inv[HH];

#pragma unroll
    for (int q = 0; q < 4; q++) s_att[tid + q * 256] = att[tid + q * 256];
    if (tid < 128) {
        uint4 raw = ((const uint4*)&g_xr_bf[(size_t)i * HCD])[tid];
        const __nv_bfloat162* p = (const __nv_bfloat162*)&raw;
#pragma unroll
        for (int q = 0; q < 4; q++) {
            float2 f = __bfloat1622float2(p[q]);
            s_xr[tid * 8 + q * 2 + 0] = f.x;
            s_xr[tid * 8 + q * 2 + 1] = f.y;
        }
    }
    __syncthreads();

    float run_m = -3.4e38f, run_s = 0.f;
    float acc0 = 0.f, acc1 = 0.f, acc2 = 0.f, acc3 = 0.f;
    int h = tid >> 5;

    for (int cb = beg; cb < end; cb += CHKF) {
        int cnt = min(CHKF, end - cb);

        for (int k = wid; k < cnt; k += 8) {
            int eid = g_adj[cb + k];
            int src = ei[eid];
            const uint4* A = (const uint4*)&g_xl_bf[(size_t)src * HCD];
            uint4* S = (uint4*)&s_xl[k][0];
#pragma unroll
            for (int it = 0; it < 4; it++) {
                int j = it * 32 + lane;
                uint4 av = A[j];
                S[j] = av;
                const __nv_bfloat162* ap = (const __nv_bfloat162*)&av;
                float v = 0.f;
#pragma unroll
                for (int q = 0; q < 4; q++) {
                    float2 fa = __bfloat1622float2(ap[q]);
                    float sx = fa.x + s_xr[j * 8 + q * 2];
                    float sy = fa.y + s_xr[j * 8 + q * 2 + 1];
                    sx = sx > 0.f ? sx : NEG_SLOPE * sx;
                    sy = sy > 0.f ? sy : NEG_SLOPE * sy;
                    v += sx * s_att[j * 8 + q * 2] + sy * s_att[j * 8 + q * 2 + 1];
                }
#pragma unroll
                for (int off = 8; off > 0; off >>= 1)
                    v += __shfl_down_sync(0xffffffffu, v, off, 16);
                if ((lane & 15) == 0) s_logit[k][it * 2 + (lane >> 4)] = v;
            }
        }
        __syncthreads();

        {
            float cm = -3.4e38f;
            for (int k = lane; k < cnt; k += 32) cm = fmaxf(cm, s_logit[k][wid]);
#pragma unroll
            for (int off = 16; off > 0; off >>= 1)
                cm = fmaxf(cm, __shfl_xor_sync(0xffffffffu, cm, off));
            float nm = fmaxf(run_m, cm);
            float csum = 0.f;
            for (int k = lane; k < cnt; k += 32) {
                float w = __expf(s_logit[k][wid] - nm);
                s_logit[k][wid] = w;
                csum += w;
            }
#pragma unroll
            for (int off = 16; off > 0; off >>= 1)
                csum += __shfl_xor_sync(0xffffffffu, csum, off);
            float scale = __expf(run_m - nm);
            run_s = run_s * scale + csum;
            run_m = nm;
            if (lane == 0) s_scale[wid] = scale;
        }
        __syncthreads();

        float sc = s_scale[h];
        acc0 *= sc; acc1 *= sc; acc2 *= sc; acc3 *= sc;
        for (int k = 0; k < cnt; k++) {
            float a = s_logit[k][h];
            uint2 raw = ((const uint2*)&s_xl[k][0])[tid];
            float2 p0 = __bfloat1622float2(*(const __nv_bfloat162*)&raw.x);
            float2 p1 = __bfloat1622float2(*(const __nv_bfloat162*)&raw.y);
            acc0 += a * p0.x;
            acc1 += a * p0.y;
            acc2 += a * p1.x;
            acc3 += a * p1.y;
        }
        __syncthreads();
    }

    if (lane == 0) s_inv[wid] = (run_s > 0.f) ? 1.f / run_s : 0.f;
    __syncthreads();
    float inv = s_inv[h];

    // pure store (residual added later by mode2 RMW epilogue)
    float4* orow = (float4*)&g_out[(size_t)i * HCD];
    orow[tid] = make_float4(acc0 * inv, acc1 * inv, acc2 * inv, acc3 * inv);
}

// ---------------- deterministic mean pool ----------------
__global__ void pool_k(const int* __restrict__ batch) {
    int g = blockIdx.x;
    __shared__ int sb, se;
    __shared__ float red[256];
    if (threadIdx.x == 0) {
        int lo = 0, hi = NN;
        while (lo < hi) { int mid = (lo + hi) >> 1; if (batch[mid] < g) lo = mid + 1; else hi = mid; }
        sb = lo;
        lo = 0; hi = NN;
        while (lo < hi) { int mid = (lo + hi) >> 1; if (batch[mid] <= g) lo = mid + 1; else hi = mid; }
        se = lo;
    }
    __syncthreads();
    int beg = sb, end = se;
    int ch = threadIdx.x & 127, half = threadIdx.x >> 7;
    float acc = 0.f;
    for (int n = beg + half; n < end; n += 2) acc += g_h[(size_t)n * CC + ch];
    red[threadIdx.x] = acc;
    __syncthreads();
    if (half == 0) {
        float v = red[ch] + red[128 + ch];
        float c = (end > beg) ? (float)(end - beg) : 1.f;
        g_pooled[g * CC + ch] = v / c;
    }
}

// ---------------- MLP head ----------------
__global__ void head_k(const float* __restrict__ W1, const float* __restrict__ b1,
                       const float* __restrict__ W2, const float* __restrict__ b2,
                       const float* __restrict__ W3, const float* __restrict__ b3,
                       float* __restrict__ out) {
    __shared__ float sp[GG][CC];
    __shared__ float h1[GG][16];
    __shared__ float h2[GG][32];
    int tid = threadIdx.x;
    for (int idx = tid; idx < GG * CC; idx += 256) sp[idx >> 7][idx & 127] = g_pooled[idx];
    __syncthreads();
    for (int idx = tid; idx < GG * 16; idx += 256) {
        int g = idx / 16, o = idx % 16;
        float s = b1[o];
        for (int k = 0; k < CC; k++) s += sp[g][k] * W1[k * 16 + o];
        h1[g][o] = s > 0.f ? s : 0.f;
    }
    __syncthreads();
    for (int idx = tid; idx < GG * 32; idx += 256) {
        int g = idx / 32, o = idx % 32;
        float s = b2[o];
        for (int k = 0; k < 16; k++) s += h1[g][k] * W2[k * 32 + o];
        h2[g][o] = s > 0.f ? s : 0.f;
    }
    __syncthreads();
    for (int idx = tid; idx < GG * 5; idx += 256) {
        int g = idx / 5, o = idx % 5;
        float s = b3[o];
        for (int k = 0; k < 32; k++) s += h2[g][k] * W3[k * 5 + o];
        out[idx] = s;
    }
}

// ---------------- launch ----------------
extern "C" void kernel_launch(void* const* d_in, const int* in_sizes, int n_in,
                              void* d_out, int out_size) {
    const float* x = (const float*)d_in[0];
    const int* ei = (const int*)d_in[1];
    const int* batch = (const int*)d_in[2];
    const float* Wl = (const float*)d_in[3];
    const float* bl = (const float*)d_in[4];
    const float* Wr = (const float*)d_in[5];
    const float* br = (const float*)d_in[6];
    const float* att = (const float*)d_in[7];
    const float* Wres = (const float*)d_in[8];
    const float* bias_attn = (const float*)d_in[9];
    const float* W_lin = (const float*)d_in[10];
    const float* b_lin = (const float*)d_in[11];
    const float* W1 = (const float*)d_in[12];
    const float* b1 = (const float*)d_in[13];
    const float* W2 = (const float*)d_in[14];
    const float* b2 = (const float*)d_in[15];
    const float* W3 = (const float*)d_in[16];
    const float* b3 = (const float*)d_in[17];
    float* out = (float*)d_out;

    cudaFuncSetAttribute(adjgemm_k, cudaFuncAttributeMaxDynamicSharedMemorySize, AG_SMEM);
    cudaFuncSetAttribute(gemm_tf32_k<8>, cudaFuncAttributeMaxDynamicSharedMemorySize,
                         (2 * SA_STAGE + 2 * 32 * 136) * 4);
    cudaFuncSetAttribute(gemm_tf32_k<4>, cudaFuncAttributeMaxDynamicSharedMemorySize,
                         (2 * SA_STAGE + 2 * 32 * 72) * 4);

    // 1. prep (x->bf16, W->packed bf16) + deg
    prep_deg_k<<<DEG_BLOCKS + XCV_BLOCKS + WPK_BLOCKS, 256>>>(ei, x, Wl, Wr);
    // 2. scan
    scan_k<<<1, 1024>>>();
    // 3. adj + xl/xr GEMMs (fused launch)
    adjgemm_k<<<ADJ_BLOCKS + 2 * GEMM_BLOCKS_PER, 256, AG_SMEM>>>(ei, bl, br);
    // 4. fused GATv2 attention (PROFILED SLOT)
    node_attn_k<<<NN, 256>>>(ei, att);
    // 5. residual GEMM (tf32), RMW-adds into g_out
    gemm_tf32_k<8><<<dim3(HCD / 128, 157), 256, (2 * SA_STAGE + 2 * 32 * 136) * 4>>>(
        x, 0, Wres, bias_attn, NN, IND, HCD, 2);
    // 6. Linear + ELU (tf32, 64-col tiles for SM fill)
    gemm_tf32_k<4><<<dim3(CC / 64, 157), 256, (2 * SA_STAGE + 2 * 32 * 72) * 4>>>(
        nullptr, 1, W_lin, b_lin, NN, HCD, CC, 3);
    // 7-8. pool + head
    pool_k<<<GG, 256>>>(batch);
    head_k<<<1, 256>>>(W1, b1, W2, b2, W3, b3, out);
}

// round 11
// speedup vs baseline: 1.0855x; 1.0727x over previous
#include <cuda_runtime.h>
#include <cuda_bf16.h>
#include <math.h>
#include <stdint.h>

#define NN 20000
#define EE 320000
#define IND 128
#define HH 8
#define CC 128
#define HCD 1024
#define GG 64
#define NEG_SLOPE 0.2f

// ---------------- scratch (static device globals; no allocation) ----------------
__device__ __nv_bfloat16 g_x_bf[(size_t)NN * IND];    // x pre-converted (5 MB)
__device__ uint32_t g_wl_pk[64 * HCD];                // Wl K-pair-packed bf16x2
__device__ uint32_t g_wr_pk[64 * HCD];                // Wr K-pair-packed bf16x2
__device__ __nv_bfloat16 g_xl_bf[(size_t)NN * HCD];   // x@Wl+bl (41 MB)
__device__ __nv_bfloat16 g_xr_bf[(size_t)NN * HCD];   // x@Wr+br (41 MB)
__device__ float g_out[(size_t)NN * HCD];             // attn aggregate (82 MB)
__device__ float g_h[(size_t)NN * CC];                // ELU(Linear) (10 MB)
__device__ float g_wfused[IND * CC];                  // Wres @ W_lin (64 KB)
__device__ float g_bfused[CC];                        // bias_attn @ W_lin + b_lin
__device__ int   g_deg[NN];                           // zero at load; re-zeroed by scan_k
__device__ int   g_rowptr[NN + 1];
__device__ int   g_cursor[NN];
__device__ int   g_adj[EE];
__device__ float g_pooled[GG * CC];

__device__ __forceinline__ uint32_t pack_bf16x2(float lo, float hi) {
    __nv_bfloat162 p = __floats2bfloat162_rn(lo, hi);
    return *(const uint32_t*)&p;
}

// ---------------- prep (deg atomics + x->bf16 + W->packed bf16), one launch ----------------
#define DEG_BLOCKS 1250
#define XCV_BLOCKS 2500
#define WPK_BLOCKS 512

__global__ void prep_deg_k(const int* __restrict__ ei, const float* __restrict__ x,
                           const float* __restrict__ Wl, const float* __restrict__ Wr) {
    int b = blockIdx.x, tid = threadIdx.x;
    if (b < DEG_BLOCKS) {
        int e = b * 256 + tid;
        if (e < EE) atomicAdd(&g_deg[ei[EE + e]], 1);
    } else if (b < DEG_BLOCKS + XCV_BLOCKS) {
        int t = (b - DEG_BLOCKS) * 256 + tid;   // < 640000 (float4 units)
        float4 v = ((const float4*)x)[t];
        uint2 o;
        o.x = pack_bf16x2(v.x, v.y);
        o.y = pack_bf16x2(v.z, v.w);
        ((uint2*)g_x_bf)[t] = o;
    } else {
        int t = (b - DEG_BLOCKS - XCV_BLOCKS) * 256 + tid;  // < 131072
        int w = t >> 16;
        int r = t & 65535;          // k2*1024 + n
        int k2 = r >> 10, n = r & 1023;
        const float* W = w ? Wr : Wl;
        uint32_t pk = pack_bf16x2(W[(2 * k2) * HCD + n], W[(2 * k2 + 1) * HCD + n]);
        (w ? g_wr_pk : g_wl_pk)[r] = pk;
    }
}

// ---------------- scan (re-zeroes g_deg for replay) ----------------
__global__ void scan_k() {
    __shared__ int warp_sums[32];
    int tid = threadIdx.x;
    int start = tid * 20;
    int v[20];
    int tot = 0;
#pragma unroll
    for (int j = 0; j < 20; j++) {
        int idx = start + j;
        int d = (idx < NN) ? g_deg[idx] : 0;
        v[j] = tot;
        tot += d;
    }
#pragma unroll
    for (int j = 0; j < 20; j++) {
        int idx = start + j;
        if (idx < NN) g_deg[idx] = 0;
    }
    int lane = tid & 31, wid = tid >> 5;
    int x = tot;
#pragma unroll
    for (int off = 1; off < 32; off <<= 1) {
        int t = __shfl_up_sync(0xffffffffu, x, off);
        if (lane >= off) x += t;
    }
    if (lane == 31) warp_sums[wid] = x;
    __syncthreads();
    if (wid == 0) {
        int w = warp_sums[lane];
#pragma unroll
        for (int off = 1; off < 32; off <<= 1) {
            int t = __shfl_up_sync(0xffffffffu, w, off);
            if (lane >= off) w += t;
        }
        warp_sums[lane] = w;
    }
    __syncthreads();
    int base = x - tot + (wid > 0 ? warp_sums[wid - 1] : 0);
#pragma unroll
    for (int j = 0; j < 20; j++) {
        int idx = start + j;
        if (idx <= NN) {
            int ex = base + v[j];
            g_rowptr[idx] = ex;
            if (idx < NN) g_cursor[idx] = ex;
        }
    }
}

// ---------------- mma helpers ----------------
__device__ __forceinline__ uint32_t f2tf32(float v) {
    uint32_t o;
    asm("cvt.rna.tf32.f32 %0, %1;" : "=r"(o) : "f"(v));
    return o;
}

__device__ __forceinline__ void mma_tf32(float c[4], uint32_t a0, uint32_t a1,
                                         uint32_t a2, uint32_t a3, uint32_t b0, uint32_t b1) {
    asm volatile(
        "mma.sync.aligned.m16n8k8.row.col.f32.tf32.tf32.f32 "
        "{%0,%1,%2,%3},{%4,%5,%6,%7},{%8,%9},{%0,%1,%2,%3};"
        : "+f"(c[0]), "+f"(c[1]), "+f"(c[2]), "+f"(c[3])
        : "r"(a0), "r"(a1), "r"(a2), "r"(a3), "r"(b0), "r"(b1));
}

__device__ __forceinline__ void mma_bf16(float c[4], uint32_t a0, uint32_t a1,
                                         uint32_t a2, uint32_t a3, uint32_t b0, uint32_t b1) {
    asm volatile(
        "mma.sync.aligned.m16n8k16.row.col.f32.bf16.bf16.f32 "
        "{%0,%1,%2,%3},{%4,%5,%6,%7},{%8,%9},{%0,%1,%2,%3};"
        : "+f"(c[0]), "+f"(c[1]), "+f"(c[2]), "+f"(c[3])
        : "r"(a0), "r"(a1), "r"(a2), "r"(a3), "r"(b0), "r"(b1));
}

__device__ __forceinline__ void cp16(uint32_t dst, const void* src, int sz) {
    asm volatile("cp.async.cg.shared.global [%0], [%1], 16, %2;"
                 :: "r"(dst), "l"(src), "r"(sz));
}
__device__ __forceinline__ void cp_commit() { asm volatile("cp.async.commit_group;"); }

// ---------------- fused adj + xl/xr bf16 cp.async GEMM ----------------
#define ADJ_BLOCKS 1250
#define GEMM_BLOCKS_PER 1256   // 157 m-tiles * 8 n-tiles
#define ASTR 20
#define BSTR 136
#define A_ST (128 * ASTR)
#define B_ST (16 * BSTR)
#define STAGE_U32 (A_ST + B_ST)
#define NSTAGE 3
#define AG_SMEM (NSTAGE * STAGE_U32 * 4)

__global__ __launch_bounds__(256) void adjgemm_k(const int* __restrict__ ei,
                                                 const float* __restrict__ bl,
                                                 const float* __restrict__ br) {
    int b = blockIdx.x, tid = threadIdx.x;
    if (b < ADJ_BLOCKS) {
        int e = b * 256 + tid;
        if (e < EE) {
            int pos = atomicAdd(&g_cursor[ei[EE + e]], 1);
            g_adj[pos] = e;
        }
        return;
    }
    extern __shared__ uint32_t sm[];
    int gb = b - ADJ_BLOCKS;
    int z = gb / GEMM_BLOCKS_PER;
    int t = gb % GEMM_BLOCKS_PER;
    int nBase = (t & 7) * 128;
    int mBase = (t >> 3) * 128;
    const uint32_t* Wpk = z ? g_wr_pk : g_wl_pk;
    const float* bias = z ? br : bl;
    __nv_bfloat16* D = z ? g_xr_bf : g_xl_bf;

    int lane = tid & 31, warp = tid >> 5;
    int wm = warp & 3, wn = warp >> 2;
    int m0 = wm * 32, n0 = wn * 64;

    uint32_t smBase = (uint32_t)__cvta_generic_to_shared(sm);

    auto issue = [&](int c) {
        int s = c % NSTAGE;
        uint32_t aAddr = smBase + (s * STAGE_U32) * 4;
        uint32_t bAddr = aAddr + A_ST * 4;
#pragma unroll
        for (int i = 0; i < 2; i++) {
            int q = tid + i * 256;
            int m = q >> 2, c4 = q & 3;
            int gr = mBase + m;
            const void* src = &g_x_bf[(size_t)min(gr, NN - 1) * IND + c * 32 + c4 * 8];
            cp16(aAddr + (m * ASTR + c4 * 4) * 4, src, gr < NN ? 16 : 0);
        }
#pragma unroll
        for (int i = 0; i < 2; i++) {
            int q = tid + i * 256;
            int k2 = q >> 5, sub = q & 31;
            const void* src = &Wpk[(c * 16 + k2) * HCD + nBase + sub * 4];
            cp16(bAddr + (k2 * BSTR + sub * 4) * 4, src, 16);
        }
        cp_commit();
    };

    float acc[2][8][4];
#pragma unroll
    for (int mt = 0; mt < 2; mt++)
#pragma unroll
        for (int nt = 0; nt < 8; nt++)
#pragma unroll
            for (int c = 0; c < 4; c++) acc[mt][nt][c] = 0.f;

    issue(0);
    issue(1);

#pragma unroll
    for (int c = 0; c < 4; c++) {
        if (c < 3) asm volatile("cp.async.wait_group 1;" ::: "memory");
        else       asm volatile("cp.async.wait_group 0;" ::: "memory");
        __syncthreads();
        if (c + 2 < 4) issue(c + 2);

        const uint32_t* sa = sm + (c % NSTAGE) * STAGE_U32;
        const uint32_t* sb = sa + A_ST;
#pragma unroll
        for (int kk = 0; kk < 2; kk++) {
            uint32_t a[2][4];
            int cidx = kk * 8 + (lane & 3);
#pragma unroll
            for (int mt = 0; mt < 2; mt++) {
                int r = m0 + mt * 16 + (lane >> 2);
                a[mt][0] = sa[r * ASTR + cidx];
                a[mt][1] = sa[(r + 8) * ASTR + cidx];
                a[mt][2] = sa[r * ASTR + cidx + 4];
                a[mt][3] = sa[(r + 8) * ASTR + cidx + 4];
            }
#pragma unroll
            for (int nt = 0; nt < 8; nt++) {
                int n = n0 + nt * 8 + (lane >> 2);
                uint32_t b0 = sb[(kk * 8 + (lane & 3)) * BSTR + n];
                uint32_t b1 = sb[(kk * 8 + (lane & 3) + 4) * BSTR + n];
                mma_bf16(acc[0][nt], a[0][0], a[0][1], a[0][2], a[0][3], b0, b1);
                mma_bf16(acc[1][nt], a[1][0], a[1][1], a[1][2], a[1][3], b0, b1);
            }
        }
        __syncthreads();
    }

#pragma unroll
    for (int mt = 0; mt < 2; mt++) {
#pragma unroll
        for (int nt = 0; nt < 8; nt++) {
            int r0 = mBase + m0 + mt * 16 + (lane >> 2);
            int cb = nBase + n0 + nt * 8 + (lane & 3) * 2;
            float bb0 = bias[cb], bb1 = bias[cb + 1];
            float v0 = acc[mt][nt][0] + bb0;
            float v1 = acc[mt][nt][1] + bb1;
            float v2 = acc[mt][nt][2] + bb0;
            float v3 = acc[mt][nt][3] + bb1;
            if (r0 < NN)
                *(__nv_bfloat162*)&D[(size_t)r0 * HCD + cb] = __floats2bfloat162_rn(v0, v1);
            if (r0 + 8 < NN)
                *(__nv_bfloat162*)&D[(size_t)(r0 + 8) * HCD + cb] = __floats2bfloat162_rn(v2, v3);
        }
    }
}

// ---------------- fused per-node GATv2 (pure aggregate; higher occupancy) ----------------
#define CHKF 8
__global__ __launch_bounds__(256, 6) void node_attn_k(const int* __restrict__ ei,
                                                      const float* __restrict__ att) {
    int i = blockIdx.x;
    int tid = threadIdx.x, lane = tid & 31, wid = tid >> 5;
    int beg = g_rowptr[i], end = g_rowptr[i + 1];

    __shared__ float s_att[HCD];
    __shared__ float s_xr[HCD];
    __shared__ __nv_bfloat16 s_xl[CHKF][HCD];
    __shared__ float s_logit[CHKF][9];
    __shared__ float s_scale[HH];
    __shared__ float s_inv[HH];

#pragma unroll
    for (int q = 0; q < 4; q++) s_att[tid + q * 256] = att[tid + q * 256];
    if (tid < 128) {
        uint4 raw = ((const uint4*)&g_xr_bf[(size_t)i * HCD])[tid];
        const __nv_bfloat162* p = (const __nv_bfloat162*)&raw;
#pragma unroll
        for (int q = 0; q < 4; q++) {
            float2 f = __bfloat1622float2(p[q]);
            s_xr[tid * 8 + q * 2 + 0] = f.x;
            s_xr[tid * 8 + q * 2 + 1] = f.y;
        }
    }
    __syncthreads();

    float run_m = -3.4e38f, run_s = 0.f;
    float acc0 = 0.f, acc1 = 0.f, acc2 = 0.f, acc3 = 0.f;
    int h = tid >> 5;

    for (int cb = beg; cb < end; cb += CHKF) {
        int cnt = min(CHKF, end - cb);

        // phase 1: logits + stage xl rows (warp per edge; <=1 edge/warp at CHKF=8)
        if (wid < cnt) {
            int k = wid;
            int eid = g_adj[cb + k];
            int src = ei[eid];
            const uint4* A = (const uint4*)&g_xl_bf[(size_t)src * HCD];
            uint4* S = (uint4*)&s_xl[k][0];
#pragma unroll
            for (int it = 0; it < 4; it++) {
                int j = it * 32 + lane;
                uint4 av = A[j];
                S[j] = av;
                const __nv_bfloat162* ap = (const __nv_bfloat162*)&av;
                float v = 0.f;
#pragma unroll
                for (int q = 0; q < 4; q++) {
                    float2 fa = __bfloat1622float2(ap[q]);
                    float sx = fa.x + s_xr[j * 8 + q * 2];
                    float sy = fa.y + s_xr[j * 8 + q * 2 + 1];
                    sx = sx > 0.f ? sx : NEG_SLOPE * sx;
                    sy = sy > 0.f ? sy : NEG_SLOPE * sy;
                    v += sx * s_att[j * 8 + q * 2] + sy * s_att[j * 8 + q * 2 + 1];
                }
#pragma unroll
                for (int off = 8; off > 0; off >>= 1)
                    v += __shfl_down_sync(0xffffffffu, v, off, 16);
                if ((lane & 15) == 0) s_logit[k][it * 2 + (lane >> 4)] = v;
            }
        }
        __syncthreads();

        // phase 2: per-head streaming stats (warp wid = head wid)
        {
            float cm = -3.4e38f;
            if (lane < cnt) cm = s_logit[lane][wid];
#pragma unroll
            for (int off = 16; off > 0; off >>= 1)
                cm = fmaxf(cm, __shfl_xor_sync(0xffffffffu, cm, off));
            float nm = fmaxf(run_m, cm);
            float csum = 0.f;
            if (lane < cnt) {
                float w = __expf(s_logit[lane][wid] - nm);
                s_logit[lane][wid] = w;
                csum = w;
            }
#pragma unroll
            for (int off = 16; off > 0; off >>= 1)
                csum += __shfl_xor_sync(0xffffffffu, csum, off);
            float scale = __expf(run_m - nm);
            run_s = run_s * scale + csum;
            run_m = nm;
            if (lane == 0) s_scale[wid] = scale;
        }
        __syncthreads();

        // phase 3: weighted aggregate from smem
        float sc = s_scale[h];
        acc0 *= sc; acc1 *= sc; acc2 *= sc; acc3 *= sc;
        for (int k = 0; k < cnt; k++) {
            float a = s_logit[k][h];
            uint2 raw = ((const uint2*)&s_xl[k][0])[tid];
            float2 p0 = __bfloat1622float2(*(const __nv_bfloat162*)&raw.x);
            float2 p1 = __bfloat1622float2(*(const __nv_bfloat162*)&raw.y);
            acc0 += a * p0.x;
            acc1 += a * p0.y;
            acc2 += a * p1.x;
            acc3 += a * p1.y;
        }
        __syncthreads();
    }

    if (lane == 0) s_inv[wid] = (run_s > 0.f) ? 1.f / run_s : 0.f;
    __syncthreads();
    float inv = s_inv[h];

    float4* orow = (float4*)&g_out[(size_t)i * HCD];
    orow[tid] = make_float4(acc0 * inv, acc1 * inv, acc2 * inv, acc3 * inv);
}

// ---------------- Wfused = Wres @ W_lin ; bfused = bias_attn @ W_lin + b_lin ----------------
__global__ void wfuse_k(const float* __restrict__ Wres, const float* __restrict__ W_lin,
                        const float* __restrict__ bias_attn, const float* __restrict__ b_lin) {
    __shared__ float s_row[HCD];
    int b = blockIdx.x, j = threadIdx.x;
    const float* row = (b < IND) ? &Wres[b * HCD] : bias_attn;
    for (int k = j; k < HCD; k += 128) s_row[k] = row[k];
    __syncthreads();
    float acc = 0.f;
    for (int k = 0; k < HCD; k++) acc += s_row[k] * W_lin[k * CC + j];
    if (b < IND) g_wfused[b * CC + j] = acc;
    else         g_bfused[j] = acc + b_lin[j];
}

// ---------------- fused Linear: ELU( g_out@W_lin + x@Wfused + bfused ) -> g_h ----------------
#define SA_STRIDE 36
#define SA_STAGE (128 * SA_STRIDE)
#define LBN 64
#define LSBS (LBN + 8)
#define LSB_STAGE (32 * LSBS)
#define LIN_SMEM ((2 * SA_STAGE + 2 * LSB_STAGE) * 4)

__global__ __launch_bounds__(256) void gemm_lin_k(const float* __restrict__ x,
                                                  const float* __restrict__ W_lin) {
    extern __shared__ uint32_t smem[];
    uint32_t* s_a = smem;
    uint32_t* s_b = smem + 2 * SA_STAGE;

    const int M = NN, N = CC, KTOT = HCD + IND;  // 1152
    int tid = threadIdx.x;
    int lane = tid & 31, warp = tid >> 5;
    int wm = warp & 3, wn = warp >> 2;
    int m0 = wm * 32, n0 = wn * 32;
    int mBase = blockIdx.y * 128, nBase = blockIdx.x * LBN;

    float acc[2][4][4];
#pragma unroll
    for (int mt = 0; mt < 2; mt++)
#pragma unroll
        for (int nt = 0; nt < 4; nt++)
#pragma unroll
            for (int c = 0; c < 4; c++) acc[mt][nt][c] = 0.f;

    int aRowBase = tid >> 3, aK4 = tid & 7;
    int bK = tid >> 3, bC = tid & 7;    // bC<8 but only 2 col-groups used (LBN=64)

    float4 aReg[4], bReg[2];
    auto loadA = [&](int k) {
#pragma unroll
        for (int i = 0; i < 4; i++) {
            int gr = mBase + aRowBase + i * 32;
            const float* src = (k < HCD) ? &g_out[(size_t)gr * HCD + k + aK4 * 4]
                                         : &x[(size_t)gr * IND + (k - HCD) + aK4 * 4];
            aReg[i] = (gr < M) ? *(const float4*)src : make_float4(0.f, 0.f, 0.f, 0.f);
        }
    };
    auto loadB = [&](int k) {
#pragma unroll
        for (int i = 0; i < 2; i++) {
            int col = nBase + ((bC & 1) + 2 * i) * 4 * 4 + (bC >> 1) * 4;  // spread 8 threads over 64 cols
            const float* src = (k < HCD) ? &W_lin[(size_t)(k + bK) * N + col]
                                         : &g_wfused[(size_t)(k - HCD + bK) * N + col];
            bReg[i] = *(const float4*)src;
        }
    };

    loadA(0);
    loadB(0);

    int s = 0;
    for (int kb = 0; kb < KTOT; kb += 32) {
#pragma unroll
        for (int i = 0; i < 4; i++) {
            int m = aRowBase + i * 32;
            uint4 at = make_uint4(f2tf32(aReg[i].x), f2tf32(aReg[i].y),
                                  f2tf32(aReg[i].z), f2tf32(aReg[i].w));
            *(uint4*)&s_a[s * SA_STAGE + m * SA_STRIDE + aK4 * 4] = at;
        }
#pragma unroll
        for (int i = 0; i < 2; i++) {
            int col = ((bC & 1) + 2 * i) * 16 + (bC >> 1) * 4;
            uint4 bt = make_uint4(f2tf32(bReg[i].x), f2tf32(bReg[i].y),
                                  f2tf32(bReg[i].z), f2tf32(bReg[i].w));
            *(uint4*)&s_b[s * LSB_STAGE + bK * LSBS + col] = bt;
        }
        __syncthreads();

        int kn = kb + 32;
        if (kn < KTOT) {
            loadA(kn);
            loadB(kn);
        }

        const uint32_t* pa = &s_a[s * SA_STAGE];
        const uint32_t* pb = &s_b[s * LSB_STAGE];
#pragma unroll
        for (int kk = 0; kk < 4; kk++) {
            uint32_t a[2][4];
#pragma unroll
            for (int mt = 0; mt < 2; mt++) {
                int r = m0 + mt * 16 + (lane >> 2);
                int c = kk * 8 + (lane & 3);
                a[mt][0] = pa[r * SA_STRIDE + c];
                a[mt][1] = pa[(r + 8) * SA_STRIDE + c];
                a[mt][2] = pa[r * SA_STRIDE + c + 4];
                a[mt][3] = pa[(r + 8) * SA_STRIDE + c + 4];
            }
#pragma unroll
            for (int nt = 0; nt < 4; nt++) {
                int n = n0 + nt * 8 + (lane >> 2);
                uint32_t b0 = pb[(kk * 8 + (lane & 3)) * LSBS + n];
                uint32_t b1 = pb[(kk * 8 + (lane & 3) + 4) * LSBS + n];
                mma_tf32(acc[0][nt], a[0][0], a[0][1], a[0][2], a[0][3], b0, b1);
                mma_tf32(acc[1][nt], a[1][0], a[1][1], a[1][2], a[1][3], b0, b1);
            }
        }
        __syncthreads();
        s ^= 1;
    }

#pragma unroll
    for (int mt = 0; mt < 2; mt++) {
#pragma unroll
        for (int nt = 0; nt < 4; nt++) {
            int r0 = mBase + m0 + mt * 16 + (lane >> 2);
            int cb = nBase + n0 + nt * 8 + (lane & 3) * 2;
            float bb0 = g_bfused[cb], bb1 = g_bfused[cb + 1];
            float v0 = acc[mt][nt][0] + bb0;
            float v1 = acc[mt][nt][1] + bb1;
            float v2 = acc[mt][nt][2] + bb0;
            float v3 = acc[mt][nt][3] + bb1;
            v0 = v0 > 0.f ? v0 : (__expf(v0) - 1.f);
            v1 = v1 > 0.f ? v1 : (__expf(v1) - 1.f);
            v2 = v2 > 0.f ? v2 : (__expf(v2) - 1.f);
            v3 = v3 > 0.f ? v3 : (__expf(v3) - 1.f);
            if (r0 < M) *(float2*)&g_h[(size_t)r0 * CC + cb] = make_float2(v0, v1);
            if (r0 + 8 < M) *(float2*)&g_h[(size_t)(r0 + 8) * CC + cb] = make_float2(v2, v3);
        }
    }
}

// ---------------- deterministic mean pool ----------------
__global__ void pool_k(const int* __restrict__ batch) {
    int g = blockIdx.x;
    __shared__ int sb, se;
    __shared__ float red[256];
    if (threadIdx.x == 0) {
        int lo = 0, hi = NN;
        while (lo < hi) { int mid = (lo + hi) >> 1; if (batch[mid] < g) lo = mid + 1; else hi = mid; }
        sb = lo;
        lo = 0; hi = NN;
        while (lo < hi) { int mid = (lo + hi) >> 1; if (batch[mid] <= g) lo = mid + 1; else hi = mid; }
        se = lo;
    }
    __syncthreads();
    int beg = sb, end = se;
    int ch = threadIdx.x & 127, half = threadIdx.x >> 7;
    float acc = 0.f;
    for (int n = beg + half; n < end; n += 2) acc += g_h[(size_t)n * CC + ch];
    red[threadIdx.x] = acc;
    __syncthreads();
    if (half == 0) {
        float v = red[ch] + red[128 + ch];
        float c = (end > beg) ? (float)(end - beg) : 1.f;
        g_pooled[g * CC + ch] = v / c;
    }
}

// ---------------- MLP head ----------------
__global__ void head_k(const float* __restrict__ W1, const float* __restrict__ b1,
                       const float* __restrict__ W2, const float* __restrict__ b2,
                       const float* __restrict__ W3, const float* __restrict__ b3,
                       float* __restrict__ out) {
    __shared__ float sp[GG][CC];
    __shared__ float h1[GG][16];
    __shared__ float h2[GG][32];
    int tid = threadIdx.x;
    for (int idx = tid; idx < GG * CC; idx += 256) sp[idx >> 7][idx & 127] = g_pooled[idx];
    __syncthreads();
    for (int idx = tid; idx < GG * 16; idx += 256) {
        int g = idx / 16, o = idx % 16;
        float s = b1[o];
        for (int k = 0; k < CC; k++) s += sp[g][k] * W1[k * 16 + o];
        h1[g][o] = s > 0.f ? s : 0.f;
    }
    __syncthreads();
    for (int idx = tid; idx < GG * 32; idx += 256) {
        int g = idx / 32, o = idx % 32;
        float s = b2[o];
        for (int k = 0; k < 16; k++) s += h1[g][k] * W2[k * 32 + o];
        h2[g][o] = s > 0.f ? s : 0.f;
    }
    __syncthreads();
    for (int idx = tid; idx < GG * 5; idx += 256) {
        int g = idx / 5, o = idx % 5;
        float s = b3[o];
        for (int k = 0; k < 32; k++) s += h2[g][k] * W3[k * 5 + o];
        out[idx] = s;
    }
}

// ---------------- launch ----------------
extern "C" void kernel_launch(void* const* d_in, const int* in_sizes, int n_in,
                              void* d_out, int out_size) {
    const float* x = (const float*)d_in[0];
    const int* ei = (const int*)d_in[1];
    const int* batch = (const int*)d_in[2];
    const float* Wl = (const float*)d_in[3];
    const float* bl = (const float*)d_in[4];
    const float* Wr = (const float*)d_in[5];
    const float* br = (const float*)d_in[6];
    const float* att = (const float*)d_in[7];
    const float* Wres = (const float*)d_in[8];
    const float* bias_attn = (const float*)d_in[9];
    const float* W_lin = (const float*)d_in[10];
    const float* b_lin = (const float*)d_in[11];
    const float* W1 = (const float*)d_in[12];
    const float* b1 = (const float*)d_in[13];
    const float* W2 = (const float*)d_in[14];
    const float* b2 = (const float*)d_in[15];
    const float* W3 = (const float*)d_in[16];
    const float* b3 = (const float*)d_in[17];
    float* out = (float*)d_out;

    cudaFuncSetAttribute(adjgemm_k, cudaFuncAttributeMaxDynamicSharedMemorySize, AG_SMEM);
    cudaFuncSetAttribute(gemm_lin_k, cudaFuncAttributeMaxDynamicSharedMemorySize, LIN_SMEM);

    // 1. prep (x->bf16, W->packed bf16) + deg
    prep_deg_k<<<DEG_BLOCKS + XCV_BLOCKS + WPK_BLOCKS, 256>>>(ei, x, Wl, Wr);
    // 2. scan
    scan_k<<<1, 1024>>>();
    // 3. adj + xl/xr GEMMs (fused launch)
    adjgemm_k<<<ADJ_BLOCKS + 2 * GEMM_BLOCKS_PER, 256, AG_SMEM>>>(ei, bl, br);
    // 4. fused GATv2 attention (PROFILED SLOT)
    node_attn_k<<<NN, 256>>>(ei, att);
    // 5. Wfused/bfused precompute (tiny)
    wfuse_k<<<IND + 1, 128>>>(Wres, W_lin, bias_attn, b_lin);
    // 6. fused Linear (residual folded in): ELU(agg@W_lin + x@Wfused + bfused)
    gemm_lin_k<<<dim3(CC / LBN, 157), 256, LIN_SMEM>>>(x, W_lin);
    // 7-8. pool + head
    pool_k<<<GG, 256>>>(batch);
    head_k<<<1, 256>>>(W1, b1, W2, b2, W3, b3, out);
}

// round 12
// speedup vs baseline: 1.3779x; 1.2695x over previous
#include <cuda_runtime.h>
#include <cuda_bf16.h>
#include <math.h>
#include <stdint.h>

#define NN 20000
#define EE 320000
#define IND 128
#define HH 8
#define CC 128
#define HCD 1024
#define GG 64
#define NEG_SLOPE 0.2f

// ---------------- scratch (static device globals; no allocation) ----------------
__device__ __nv_bfloat16 g_x_bf[(size_t)NN * IND];    // x pre-converted (5 MB)
__device__ uint32_t g_wl_pk[64 * HCD];                // Wl K-pair-packed bf16x2
__device__ uint32_t g_wr_pk[64 * HCD];                // Wr K-pair-packed bf16x2
__device__ __nv_bfloat16 g_xl_bf[(size_t)NN * HCD];   // x@Wl+bl (41 MB)
__device__ __nv_bfloat16 g_xr_bf[(size_t)NN * HCD];   // x@Wr+br (41 MB)
__device__ float g_out[(size_t)NN * HCD];             // attn aggregate (82 MB)
__device__ float g_h[(size_t)NN * CC];                // ELU(Linear) (10 MB)
__device__ float g_wfused[IND * CC];                  // Wres @ W_lin
__device__ float g_bfused[CC];                        // bias_attn @ W_lin + b_lin
__device__ int   g_deg[NN];                           // zero at load; re-zeroed by scan_k
__device__ int   g_rowptr[NN + 1];
__device__ int   g_cursor[NN];
__device__ int   g_adj[EE];
__device__ float g_pooled[GG * CC];

__device__ __forceinline__ uint32_t pack_bf16x2(float lo, float hi) {
    __nv_bfloat162 p = __floats2bfloat162_rn(lo, hi);
    return *(const uint32_t*)&p;
}

// ---------------- prep (deg atomics + x->bf16 + W->packed bf16), one launch ----------------
#define DEG_BLOCKS 1250
#define XCV_BLOCKS 2500
#define WPK_BLOCKS 512

__global__ void prep_deg_k(const int* __restrict__ ei, const float* __restrict__ x,
                           const float* __restrict__ Wl, const float* __restrict__ Wr) {
    int b = blockIdx.x, tid = threadIdx.x;
    if (b < DEG_BLOCKS) {
        int e = b * 256 + tid;
        if (e < EE) atomicAdd(&g_deg[ei[EE + e]], 1);
    } else if (b < DEG_BLOCKS + XCV_BLOCKS) {
        int t = (b - DEG_BLOCKS) * 256 + tid;
        float4 v = ((const float4*)x)[t];
        uint2 o;
        o.x = pack_bf16x2(v.x, v.y);
        o.y = pack_bf16x2(v.z, v.w);
        ((uint2*)g_x_bf)[t] = o;
    } else {
        int t = (b - DEG_BLOCKS - XCV_BLOCKS) * 256 + tid;
        int w = t >> 16;
        int r = t & 65535;
        int k2 = r >> 10, n = r & 1023;
        const float* W = w ? Wr : Wl;
        uint32_t pk = pack_bf16x2(W[(2 * k2) * HCD + n], W[(2 * k2 + 1) * HCD + n]);
        (w ? g_wr_pk : g_wl_pk)[r] = pk;
    }
}

// ---------------- scan (re-zeroes g_deg for replay) ----------------
__global__ void scan_k() {
    __shared__ int warp_sums[32];
    int tid = threadIdx.x;
    int start = tid * 20;
    int v[20];
    int tot = 0;
#pragma unroll
    for (int j = 0; j < 20; j++) {
        int idx = start + j;
        int d = (idx < NN) ? g_deg[idx] : 0;
        v[j] = tot;
        tot += d;
    }
#pragma unroll
    for (int j = 0; j < 20; j++) {
        int idx = start + j;
        if (idx < NN) g_deg[idx] = 0;
    }
    int lane = tid & 31, wid = tid >> 5;
    int x = tot;
#pragma unroll
    for (int off = 1; off < 32; off <<= 1) {
        int t = __shfl_up_sync(0xffffffffu, x, off);
        if (lane >= off) x += t;
    }
    if (lane == 31) warp_sums[wid] = x;
    __syncthreads();
    if (wid == 0) {
        int w = warp_sums[lane];
#pragma unroll
        for (int off = 1; off < 32; off <<= 1) {
            int t = __shfl_up_sync(0xffffffffu, w, off);
            if (lane >= off) w += t;
        }
        warp_sums[lane] = w;
    }
    __syncthreads();
    int base = x - tot + (wid > 0 ? warp_sums[wid - 1] : 0);
#pragma unroll
    for (int j = 0; j < 20; j++) {
        int idx = start + j;
        if (idx <= NN) {
            int ex = base + v[j];
            g_rowptr[idx] = ex;
            if (idx < NN) g_cursor[idx] = ex;
        }
    }
}

// ---------------- mma helpers ----------------
__device__ __forceinline__ uint32_t f2tf32(float v) {
    uint32_t o;
    asm("cvt.rna.tf32.f32 %0, %1;" : "=r"(o) : "f"(v));
    return o;
}

__device__ __forceinline__ void mma_tf32(float c[4], uint32_t a0, uint32_t a1,
                                         uint32_t a2, uint32_t a3, uint32_t b0, uint32_t b1) {
    asm volatile(
        "mma.sync.aligned.m16n8k8.row.col.f32.tf32.tf32.f32 "
        "{%0,%1,%2,%3},{%4,%5,%6,%7},{%8,%9},{%0,%1,%2,%3};"
        : "+f"(c[0]), "+f"(c[1]), "+f"(c[2]), "+f"(c[3])
        : "r"(a0), "r"(a1), "r"(a2), "r"(a3), "r"(b0), "r"(b1));
}

__device__ __forceinline__ void mma_bf16(float c[4], uint32_t a0, uint32_t a1,
                                         uint32_t a2, uint32_t a3, uint32_t b0, uint32_t b1) {
    asm volatile(
        "mma.sync.aligned.m16n8k16.row.col.f32.bf16.bf16.f32 "
        "{%0,%1,%2,%3},{%4,%5,%6,%7},{%8,%9},{%0,%1,%2,%3};"
        : "+f"(c[0]), "+f"(c[1]), "+f"(c[2]), "+f"(c[3])
        : "r"(a0), "r"(a1), "r"(a2), "r"(a3), "r"(b0), "r"(b1));
}

__device__ __forceinline__ void cp16(uint32_t dst, const void* src, int sz) {
    asm volatile("cp.async.cg.shared.global [%0], [%1], 16, %2;"
                 :: "r"(dst), "l"(src), "r"(sz));
}
__device__ __forceinline__ void cp_commit() { asm volatile("cp.async.commit_group;"); }

// ---------------- fused adj + xl/xr bf16 cp.async GEMM ----------------
#define ADJ_BLOCKS 1250
#define GEMM_BLOCKS_PER 1256
#define ASTR 20
#define BSTR 136
#define A_ST (128 * ASTR)
#define B_ST (16 * BSTR)
#define STAGE_U32 (A_ST + B_ST)
#define NSTAGE 3
#define AG_SMEM (NSTAGE * STAGE_U32 * 4)

__global__ __launch_bounds__(256) void adjgemm_k(const int* __restrict__ ei,
                                                 const float* __restrict__ bl,
                                                 const float* __restrict__ br) {
    int b = blockIdx.x, tid = threadIdx.x;
    if (b < ADJ_BLOCKS) {
        int e = b * 256 + tid;
        if (e < EE) {
            int pos = atomicAdd(&g_cursor[ei[EE + e]], 1);
            g_adj[pos] = e;
        }
        return;
    }
    extern __shared__ uint32_t sm[];
    int gb = b - ADJ_BLOCKS;
    int z = gb / GEMM_BLOCKS_PER;
    int t = gb % GEMM_BLOCKS_PER;
    int nBase = (t & 7) * 128;
    int mBase = (t >> 3) * 128;
    const uint32_t* Wpk = z ? g_wr_pk : g_wl_pk;
    const float* bias = z ? br : bl;
    __nv_bfloat16* D = z ? g_xr_bf : g_xl_bf;

    int lane = tid & 31, warp = tid >> 5;
    int wm = warp & 3, wn = warp >> 2;
    int m0 = wm * 32, n0 = wn * 64;

    uint32_t smBase = (uint32_t)__cvta_generic_to_shared(sm);

    auto issue = [&](int c) {
        int s = c % NSTAGE;
        uint32_t aAddr = smBase + (s * STAGE_U32) * 4;
        uint32_t bAddr = aAddr + A_ST * 4;
#pragma unroll
        for (int i = 0; i < 2; i++) {
            int q = tid + i * 256;
            int m = q >> 2, c4 = q & 3;
            int gr = mBase + m;
            const void* src = &g_x_bf[(size_t)min(gr, NN - 1) * IND + c * 32 + c4 * 8];
            cp16(aAddr + (m * ASTR + c4 * 4) * 4, src, gr < NN ? 16 : 0);
        }
#pragma unroll
        for (int i = 0; i < 2; i++) {
            int q = tid + i * 256;
            int k2 = q >> 5, sub = q & 31;
            const void* src = &Wpk[(c * 16 + k2) * HCD + nBase + sub * 4];
            cp16(bAddr + (k2 * BSTR + sub * 4) * 4, src, 16);
        }
        cp_commit();
    };

    float acc[2][8][4];
#pragma unroll
    for (int mt = 0; mt < 2; mt++)
#pragma unroll
        for (int nt = 0; nt < 8; nt++)
#pragma unroll
            for (int c = 0; c < 4; c++) acc[mt][nt][c] = 0.f;

    issue(0);
    issue(1);

#pragma unroll
    for (int c = 0; c < 4; c++) {
        if (c < 3) asm volatile("cp.async.wait_group 1;" ::: "memory");
        else       asm volatile("cp.async.wait_group 0;" ::: "memory");
        __syncthreads();
        if (c + 2 < 4) issue(c + 2);

        const uint32_t* sa = sm + (c % NSTAGE) * STAGE_U32;
        const uint32_t* sb = sa + A_ST;
#pragma unroll
        for (int kk = 0; kk < 2; kk++) {
            uint32_t a[2][4];
            int cidx = kk * 8 + (lane & 3);
#pragma unroll
            for (int mt = 0; mt < 2; mt++) {
                int r = m0 + mt * 16 + (lane >> 2);
                a[mt][0] = sa[r * ASTR + cidx];
                a[mt][1] = sa[(r + 8) * ASTR + cidx];
                a[mt][2] = sa[r * ASTR + cidx + 4];
                a[mt][3] = sa[(r + 8) * ASTR + cidx + 4];
            }
#pragma unroll
            for (int nt = 0; nt < 8; nt++) {
                int n = n0 + nt * 8 + (lane >> 2);
                uint32_t b0 = sb[(kk * 8 + (lane & 3)) * BSTR + n];
                uint32_t b1 = sb[(kk * 8 + (lane & 3) + 4) * BSTR + n];
                mma_bf16(acc[0][nt], a[0][0], a[0][1], a[0][2], a[0][3], b0, b1);
                mma_bf16(acc[1][nt], a[1][0], a[1][1], a[1][2], a[1][3], b0, b1);
            }
        }
        __syncthreads();
    }

#pragma unroll
    for (int mt = 0; mt < 2; mt++) {
#pragma unroll
        for (int nt = 0; nt < 8; nt++) {
            int r0 = mBase + m0 + mt * 16 + (lane >> 2);
            int cb = nBase + n0 + nt * 8 + (lane & 3) * 2;
            float bb0 = bias[cb], bb1 = bias[cb + 1];
            float v0 = acc[mt][nt][0] + bb0;
            float v1 = acc[mt][nt][1] + bb1;
            float v2 = acc[mt][nt][2] + bb0;
            float v3 = acc[mt][nt][3] + bb1;
            if (r0 < NN)
                *(__nv_bfloat162*)&D[(size_t)r0 * HCD + cb] = __floats2bfloat162_rn(v0, v1);
            if (r0 + 8 < NN)
                *(__nv_bfloat162*)&D[(size_t)(r0 + 8) * HCD + cb] = __floats2bfloat162_rn(v2, v3);
        }
    }
}

// ---------------- per-node GATv2: ONE WARP PER NODE, register-resident ----------------
// Lane layout: group (it, lane) covers channels (it*32+lane)*8 .. +7 ; head = it*2 + (lane>>4).
// Online softmax state per lane: m[it], s[it] for its 4 heads (consistent across 16-lane segment).
__global__ __launch_bounds__(128) void node_attn_k(const int* __restrict__ ei,
                                                   const float* __restrict__ att) {
    __shared__ float s_att[HCD];   // 4 KB, shared by 4 warps
    int tid = threadIdx.x, lane = tid & 31, wid = tid >> 5;
    for (int q = tid; q < HCD; q += 128) s_att[q] = att[q];
    __syncthreads();

    int i = blockIdx.x * 4 + wid;   // NN = 20000 = 5000*4, exact
    int beg = g_rowptr[i], end = g_rowptr[i + 1];

    // xr row -> registers
    float xr[4][8];
#pragma unroll
    for (int it = 0; it < 4; it++) {
        uint4 r = ((const uint4*)&g_xr_bf[(size_t)i * HCD])[it * 32 + lane];
        const __nv_bfloat162* p = (const __nv_bfloat162*)&r;
#pragma unroll
        for (int q2 = 0; q2 < 4; q2++) {
            float2 f = __bfloat1622float2(p[q2]);
            xr[it][q2 * 2] = f.x;
            xr[it][q2 * 2 + 1] = f.y;
        }
    }

    float m[4], s[4], acc[4][8];
#pragma unroll
    for (int it = 0; it < 4; it++) {
        m[it] = -3.4e38f;
        s[it] = 0.f;
#pragma unroll
        for (int q = 0; q < 8; q++) acc[it][q] = 0.f;
    }

    for (int cb = beg; cb < end; cb += 32) {
        int cnt = min(32, end - cb);
        int mysrc = 0;
        if (lane < cnt) mysrc = ei[g_adj[cb + lane]];

        for (int e = 0; e < cnt; e++) {
            int src = __shfl_sync(0xffffffffu, mysrc, e);
            const uint4* A = (const uint4*)&g_xl_bf[(size_t)src * HCD];
#pragma unroll
            for (int it = 0; it < 4; it++) {
                uint4 raw = A[it * 32 + lane];
                const __nv_bfloat162* p = (const __nv_bfloat162*)&raw;
                float val[8];
#pragma unroll
                for (int q2 = 0; q2 < 4; q2++) {
                    float2 f = __bfloat1622float2(p[q2]);
                    val[q2 * 2] = f.x;
                    val[q2 * 2 + 1] = f.y;
                }
                const float4* ap = (const float4*)&s_att[(it * 32 + lane) * 8];
                float4 a0 = ap[0], a1 = ap[1];
                float v = 0.f;
                {
                    float t0 = val[0] + xr[it][0]; t0 = t0 > 0.f ? t0 : NEG_SLOPE * t0;
                    float t1 = val[1] + xr[it][1]; t1 = t1 > 0.f ? t1 : NEG_SLOPE * t1;
                    float t2 = val[2] + xr[it][2]; t2 = t2 > 0.f ? t2 : NEG_SLOPE * t2;
                    float t3 = val[3] + xr[it][3]; t3 = t3 > 0.f ? t3 : NEG_SLOPE * t3;
                    float t4 = val[4] + xr[it][4]; t4 = t4 > 0.f ? t4 : NEG_SLOPE * t4;
                    float t5 = val[5] + xr[it][5]; t5 = t5 > 0.f ? t5 : NEG_SLOPE * t5;
                    float t6 = val[6] + xr[it][6]; t6 = t6 > 0.f ? t6 : NEG_SLOPE * t6;
                    float t7 = val[7] + xr[it][7]; t7 = t7 > 0.f ? t7 : NEG_SLOPE * t7;
                    v = t0 * a0.x + t1 * a0.y + t2 * a0.z + t3 * a0.w
                      + t4 * a1.x + t5 * a1.y + t6 * a1.z + t7 * a1.w;
                }
                // reduce within 16-lane segment (same value in all lanes of segment)
                v += __shfl_xor_sync(0xffffffffu, v, 1);
                v += __shfl_xor_sync(0xffffffffu, v, 2);
                v += __shfl_xor_sync(0xffffffffu, v, 4);
                v += __shfl_xor_sync(0xffffffffu, v, 8);
                // online softmax update + accumulate (head it*2+(lane>>4))
                float nm = fmaxf(m[it], v);
                float corr = __expf(m[it] - nm);
                float w = __expf(v - nm);
                s[it] = s[it] * corr + w;
                m[it] = nm;
#pragma unroll
                for (int q = 0; q < 8; q++)
                    acc[it][q] = acc[it][q] * corr + w * val[q];
            }
        }
    }

    // normalize + store
#pragma unroll
    for (int it = 0; it < 4; it++) {
        float inv = (s[it] > 0.f) ? 1.f / s[it] : 0.f;
        float4* dst = (float4*)&g_out[(size_t)i * HCD + (size_t)(it * 32 + lane) * 8];
        dst[0] = make_float4(acc[it][0] * inv, acc[it][1] * inv,
                             acc[it][2] * inv, acc[it][3] * inv);
        dst[1] = make_float4(acc[it][4] * inv, acc[it][5] * inv,
                             acc[it][6] * inv, acc[it][7] * inv);
    }
}

// ---------------- Wfused = Wres @ W_lin ; bfused = bias_attn @ W_lin + b_lin ----------------
__global__ void wfuse_k(const float* __restrict__ Wres, const float* __restrict__ W_lin,
                        const float* __restrict__ bias_attn, const float* __restrict__ b_lin) {
    __shared__ float s_row[HCD];
    int b = blockIdx.x, j = threadIdx.x;
    const float* row = (b < IND) ? &Wres[b * HCD] : bias_attn;
    for (int k = j; k < HCD; k += 128) s_row[k] = row[k];
    __syncthreads();
    float acc = 0.f;
    for (int k = 0; k < HCD; k++) acc += s_row[k] * W_lin[k * CC + j];
    if (b < IND) g_wfused[b * CC + j] = acc;
    else         g_bfused[j] = acc + b_lin[j];
}

// ---------------- fused Linear: ELU( g_out@W_lin + x@Wfused + bfused ) -> g_h ----------------
#define SA_STRIDE 36
#define SA_STAGE (128 * SA_STRIDE)
#define LBN 64
#define LSBS (LBN + 8)
#define LSB_STAGE (32 * LSBS)
#define LIN_SMEM ((2 * SA_STAGE + 2 * LSB_STAGE) * 4)

__global__ __launch_bounds__(256) void gemm_lin_k(const float* __restrict__ x,
                                                  const float* __restrict__ W_lin) {
    extern __shared__ uint32_t smem[];
    uint32_t* s_a = smem;
    uint32_t* s_b = smem + 2 * SA_STAGE;

    const int M = NN, N = CC, KTOT = HCD + IND;
    int tid = threadIdx.x;
    int lane = tid & 31, warp = tid >> 5;
    int wm = warp & 3, wn = warp >> 2;
    int m0 = wm * 32, n0 = wn * 32;
    int mBase = blockIdx.y * 128, nBase = blockIdx.x * LBN;

    float acc[2][4][4];
#pragma unroll
    for (int mt = 0; mt < 2; mt++)
#pragma unroll
        for (int nt = 0; nt < 4; nt++)
#pragma unroll
            for (int c = 0; c < 4; c++) acc[mt][nt][c] = 0.f;

    int aRowBase = tid >> 3, aK4 = tid & 7;
    int bK = tid >> 3, bC = tid & 7;

    float4 aReg[4], bReg[2];
    auto loadA = [&](int k) {
#pragma unroll
        for (int i = 0; i < 4; i++) {
            int gr = mBase + aRowBase + i * 32;
            const float* src = (k < HCD) ? &g_out[(size_t)gr * HCD + k + aK4 * 4]
                                         : &x[(size_t)gr * IND + (k - HCD) + aK4 * 4];
            aReg[i] = (gr < M) ? *(const float4*)src : make_float4(0.f, 0.f, 0.f, 0.f);
        }
    };
    auto loadB = [&](int k) {
#pragma unroll
        for (int i = 0; i < 2; i++) {
            int col = nBase + ((bC & 1) + 2 * i) * 4 * 4 + (bC >> 1) * 4;
            const float* src = (k < HCD) ? &W_lin[(size_t)(k + bK) * N + col]
                                         : &g_wfused[(size_t)(k - HCD + bK) * N + col];
            bReg[i] = *(const float4*)src;
        }
    };

    loadA(0);
    loadB(0);

    int s = 0;
    for (int kb = 0; kb < KTOT; kb += 32) {
#pragma unroll
        for (int i = 0; i < 4; i++) {
            int m = aRowBase + i * 32;
            uint4 at = make_uint4(f2tf32(aReg[i].x), f2tf32(aReg[i].y),
                                  f2tf32(aReg[i].z), f2tf32(aReg[i].w));
            *(uint4*)&s_a[s * SA_STAGE + m * SA_STRIDE + aK4 * 4] = at;
        }
#pragma unroll
        for (int i = 0; i < 2; i++) {
            int col = ((bC & 1) + 2 * i) * 16 + (bC >> 1) * 4;
            uint4 bt = make_uint4(f2tf32(bReg[i].x), f2tf32(bReg[i].y),
                                  f2tf32(bReg[i].z), f2tf32(bReg[i].w));
            *(uint4*)&s_b[s * LSB_STAGE + bK * LSBS + col] = bt;
        }
        __syncthreads();

        int kn = kb + 32;
        if (kn < KTOT) {
            loadA(kn);
            loadB(kn);
        }

        const uint32_t* pa = &s_a[s * SA_STAGE];
        const uint32_t* pb = &s_b[s * LSB_STAGE];
#pragma unroll
        for (int kk = 0; kk < 4; kk++) {
            uint32_t a[2][4];
#pragma unroll
            for (int mt = 0; mt < 2; mt++) {
                int r = m0 + mt * 16 + (lane >> 2);
                int c = kk * 8 + (lane & 3);
                a[mt][0] = pa[r * SA_STRIDE + c];
                a[mt][1] = pa[(r + 8) * SA_STRIDE + c];
                a[mt][2] = pa[r * SA_STRIDE + c + 4];
                a[mt][3] = pa[(r + 8) * SA_STRIDE + c + 4];
            }
#pragma unroll
            for (int nt = 0; nt < 4; nt++) {
                int n = n0 + nt * 8 + (lane >> 2);
                uint32_t b0 = pb[(kk * 8 + (lane & 3)) * LSBS + n];
                uint32_t b1 = pb[(kk * 8 + (lane & 3) + 4) * LSBS + n];
                mma_tf32(acc[0][nt], a[0][0], a[0][1], a[0][2], a[0][3], b0, b1);
                mma_tf32(acc[1][nt], a[1][0], a[1][1], a[1][2], a[1][3], b0, b1);
            }
        }
        __syncthreads();
        s ^= 1;
    }

#pragma unroll
    for (int mt = 0; mt < 2; mt++) {
#pragma unroll
        for (int nt = 0; nt < 4; nt++) {
            int r0 = mBase + m0 + mt * 16 + (lane >> 2);
            int cb = nBase + n0 + nt * 8 + (lane & 3) * 2;
            float bb0 = g_bfused[cb], bb1 = g_bfused[cb + 1];
            float v0 = acc[mt][nt][0] + bb0;
            float v1 = acc[mt][nt][1] + bb1;
            float v2 = acc[mt][nt][2] + bb0;
            float v3 = acc[mt][nt][3] + bb1;
            v0 = v0 > 0.f ? v0 : (__expf(v0) - 1.f);
            v1 = v1 > 0.f ? v1 : (__expf(v1) - 1.f);
            v2 = v2 > 0.f ? v2 : (__expf(v2) - 1.f);
            v3 = v3 > 0.f ? v3 : (__expf(v3) - 1.f);
            if (r0 < M) *(float2*)&g_h[(size_t)r0 * CC + cb] = make_float2(v0, v1);
            if (r0 + 8 < M) *(float2*)&g_h[(size_t)(r0 + 8) * CC + cb] = make_float2(v2, v3);
        }
    }
}

// ---------------- deterministic mean pool ----------------
__global__ void pool_k(const int* __restrict__ batch) {
    int g = blockIdx.x;
    __shared__ int sb, se;
    __shared__ float red[256];
    if (threadIdx.x == 0) {
        int lo = 0, hi = NN;
        while (lo < hi) { int mid = (lo + hi) >> 1; if (batch[mid] < g) lo = mid + 1; else hi = mid; }
        sb = lo;
        lo = 0; hi = NN;
        while (lo < hi) { int mid = (lo + hi) >> 1; if (batch[mid] <= g) lo = mid + 1; else hi = mid; }
        se = lo;
    }
    __syncthreads();
    int beg = sb, end = se;
    int ch = threadIdx.x & 127, half = threadIdx.x >> 7;
    float acc = 0.f;
    for (int n = beg + half; n < end; n += 2) acc += g_h[(size_t)n * CC + ch];
    red[threadIdx.x] = acc;
    __syncthreads();
    if (half == 0) {
        float v = red[ch] + red[128 + ch];
        float c = (end > beg) ? (float)(end - beg) : 1.f;
        g_pooled[g * CC + ch] = v / c;
    }
}

// ---------------- MLP head ----------------
__global__ void head_k(const float* __restrict__ W1, const float* __restrict__ b1,
                       const float* __restrict__ W2, const float* __restrict__ b2,
                       const float* __restrict__ W3, const float* __restrict__ b3,
                       float* __restrict__ out) {
    __shared__ float sp[GG][CC];
    __shared__ float h1[GG][16];
    __shared__ float h2[GG][32];
    int tid = threadIdx.x;
    for (int idx = tid; idx < GG * CC; idx += 256) sp[idx >> 7][idx & 127] = g_pooled[idx];
    __syncthreads();
    for (int idx = tid; idx < GG * 16; idx += 256) {
        int g = idx / 16, o = idx % 16;
        float s = b1[o];
        for (int k = 0; k < CC; k++) s += sp[g][k] * W1[k * 16 + o];
        h1[g][o] = s > 0.f ? s : 0.f;
    }
    __syncthreads();
    for (int idx = tid; idx < GG * 32; idx += 256) {
        int g = idx / 32, o = idx % 32;
        float s = b2[o];
        for (int k = 0; k < 16; k++) s += h1[g][k] * W2[k * 32 + o];
        h2[g][o] = s > 0.f ? s : 0.f;
    }
    __syncthreads();
    for (int idx = tid; idx < GG * 5; idx += 256) {
        int g = idx / 5, o = idx % 5;
        float s = b3[o];
        for (int k = 0; k < 32; k++) s += h2[g][k] * W3[k * 5 + o];
        out[idx] = s;
    }
}

// ---------------- launch ----------------
extern "C" void kernel_launch(void* const* d_in, const int* in_sizes, int n_in,
                              void* d_out, int out_size) {
    const float* x = (const float*)d_in[0];
    const int* ei = (const int*)d_in[1];
    const int* batch = (const int*)d_in[2];
    const float* Wl = (const float*)d_in[3];
    const float* bl = (const float*)d_in[4];
    const float* Wr = (const float*)d_in[5];
    const float* br = (const float*)d_in[6];
    const float* att = (const float*)d_in[7];
    const float* Wres = (const float*)d_in[8];
    const float* bias_attn = (const float*)d_in[9];
    const float* W_lin = (const float*)d_in[10];
    const float* b_lin = (const float*)d_in[11];
    const float* W1 = (const float*)d_in[12];
    const float* b1 = (const float*)d_in[13];
    const float* W2 = (const float*)d_in[14];
    const float* b2 = (const float*)d_in[15];
    const float* W3 = (const float*)d_in[16];
    const float* b3 = (const float*)d_in[17];
    float* out = (float*)d_out;

    cudaFuncSetAttribute(adjgemm_k, cudaFuncAttributeMaxDynamicSharedMemorySize, AG_SMEM);
    cudaFuncSetAttribute(gemm_lin_k, cudaFuncAttributeMaxDynamicSharedMemorySize, LIN_SMEM);

    // 1. prep (x->bf16, W->packed bf16) + deg
    prep_deg_k<<<DEG_BLOCKS + XCV_BLOCKS + WPK_BLOCKS, 256>>>(ei, x, Wl, Wr);
    // 2. scan
    scan_k<<<1, 1024>>>();
    // 3. adj + xl/xr GEMMs (fused launch)
    adjgemm_k<<<ADJ_BLOCKS + 2 * GEMM_BLOCKS_PER, 256, AG_SMEM>>>(ei, bl, br);
    // 4. warp-per-node GATv2 attention (PROFILED SLOT)
    node_attn_k<<<NN / 4, 128>>>(ei, att);
    // 5. Wfused/bfused precompute (tiny)
    wfuse_k<<<IND + 1, 128>>>(Wres, W_lin, bias_attn, b_lin);
    // 6. fused Linear (residual folded in): ELU(agg@W_lin + x@Wfused + bfused)
    gemm_lin_k<<<dim3(CC / LBN, 157), 256, LIN_SMEM>>>(x, W_lin);
    // 7-8. pool + head
    pool_k<<<GG, 256>>>(batch);
    head_k<<<1, 256>>>(W1, b1, W2, b2, W3, b3, out);
}